// round 2
// baseline (speedup 1.0000x reference)
#include <cuda_runtime.h>
#include <math.h>

#define B_   64
#define T_   512
#define IN_  128
#define H_   512
#define G4_  2048   // 4*H
#define OUT_ 128

#define NBLK 128    // persistent grid: H_/4 blocks, all co-resident (<=148 SMs)
#define NTHR 256

// ---------------- scratch (static device memory; no allocs) ----------------
__device__ float g_xp[(size_t)B_ * T_ * G4_];     // gate preactivations (layer0 then layer1)
__device__ float g_hseq[(size_t)B_ * T_ * H_];    // layer-0 hidden states for all t
__device__ float g_h1[2][B_ * H_];                // layer-1 h ping-pong
__device__ unsigned int g_bar;                    // grid barrier counter

__global__ void bar_init_kernel() { g_bar = 0u; }

// ---------------------------------------------------------------------------
// SGEMM: C[M,N] = A[M,K] @ W[N,K]^T + b1[N] + b2[N]
// ---------------------------------------------------------------------------
__global__ __launch_bounds__(256) void gemm_bias_kernel(
    const float* __restrict__ A, const float* __restrict__ W,
    const float* __restrict__ b1, const float* __restrict__ b2,
    float* __restrict__ C, int M, int N, int K)
{
    __shared__ float As[8][132];
    __shared__ float Bs[8][132];

    const int tx = threadIdx.x;
    const int tn = tx & 15;
    const int tm = tx >> 4;
    const int m0 = blockIdx.y * 128;
    const int n0 = blockIdx.x * 128;

    float acc[8][8];
#pragma unroll
    for (int i = 0; i < 8; i++)
#pragma unroll
        for (int j = 0; j < 8; j++) acc[i][j] = 0.f;

    for (int kk = 0; kk < K; kk += 8) {
#pragma unroll
        for (int i = 0; i < 4; i++) {
            int idx = tx + i * 256;
            int r = idx >> 3;
            int k = idx & 7;
            As[k][r] = A[(size_t)(m0 + r) * K + kk + k];
            Bs[k][r] = W[(size_t)(n0 + r) * K + kk + k];
        }
        __syncthreads();
#pragma unroll
        for (int k = 0; k < 8; k++) {
            float a[8], bb[8];
#pragma unroll
            for (int i = 0; i < 8; i++) a[i]  = As[k][tm * 8 + i];
#pragma unroll
            for (int i = 0; i < 8; i++) bb[i] = Bs[k][tn * 8 + i];
#pragma unroll
            for (int i = 0; i < 8; i++)
#pragma unroll
                for (int j = 0; j < 8; j++)
                    acc[i][j] += a[i] * bb[j];
        }
        __syncthreads();
    }

#pragma unroll
    for (int i = 0; i < 8; i++) {
        int m = m0 + tm * 8 + i;
#pragma unroll
        for (int j = 0; j < 8; j++) {
            int n = n0 + tn * 8 + j;
            C[(size_t)m * N + n] = acc[i][j] + b1[n] + b2[n];
        }
    }
}

// ---------------------------------------------------------------------------
// Persistent LSTM recurrence for one layer. 128 blocks x 256 threads.
// Block bk owns 4 hidden units j0=bk*4 => 16 gate columns (cc: gg=cc>>2, u=cc&3).
// W_hh slice kept in SMEM across all T steps; cell state in SMEM.
// Grid barrier between steps (atomic counter, zeroed by bar_init_kernel).
//
// mode 0: h stored in hseq layout [B][T][H]   (row stride T*H, step offset t*H)
// mode 1: h in ping-pong buffers   [2][B][H]  (row stride H,   step offset (t&1)*B*H)
// ---------------------------------------------------------------------------
#define WS(c,k)    ws[(c) * 514 + (k)]
#define HSX(g,r,k) hsm[((g) * 64 + (r)) * 33 + (k)]

__global__ __launch_bounds__(NTHR, 1) void lstm_persist_kernel(
    const float* __restrict__ xp,    // [B*T, 2048], row = b*T + t
    const float* __restrict__ Whh,   // [2048, 512]
    float* __restrict__ hbase,       // base of h storage (see mode)
    int mode)
{
    extern __shared__ float smem[];
    float* ws  = smem;                      // 16 x 514
    float* hsm = ws + 16 * 514;             // 2 x 64 x 33
    float* ps  = hsm + 2 * 64 * 33;         // 1024 (partials, then gates)
    float* cs  = ps + 1024;                 // 256 cell states (64 rows x 4 units)

    const int tx   = threadIdx.x;
    const int colg = tx & 7;                // 2 cols: 2*colg, 2*colg+1
    const int rowg = (tx >> 3) & 15;        // 4 rows: rowg*4 .. +3
    const int kg   = tx >> 7;               // K-split group (0 or 1)
    const int j0   = blockIdx.x * 4;

    const long long rs    = (mode == 0) ? (long long)T_ * H_ : (long long)H_;
    const unsigned  nblk  = gridDim.x;

    // load W_hh slice once: ws[cc][k] = Whh[(gg*H + j0 + u)*H + k], cc=gg*4+u
#pragma unroll
    for (int i = 0; i < 32; i++) {
        int idx = tx + i * 256;             // 0..8191
        int cc  = idx >> 9;                 // 0..15
        int k   = idx & 511;
        int gg  = cc >> 2;
        int u   = cc & 3;
        WS(cc, k) = Whh[(size_t)(gg * H_ + j0 + u) * H_ + k];
    }
    __syncthreads();

    for (int t = 0; t < T_; t++) {
        float acc[4][2];
#pragma unroll
        for (int i = 0; i < 4; i++) { acc[i][0] = 0.f; acc[i][1] = 0.f; }

        if (t > 0) {
            const long long inoff = (mode == 0) ? (long long)(t - 1) * H_
                                                : (long long)(((t & 1) ^ 1)) * B_ * H_;
            const float* hin = hbase + inoff;

            for (int kk = 0; kk < 256; kk += 32) {
                // stage both K-groups' 64x32 h chunks (L2 reads, bypass L1)
#pragma unroll
                for (int i = 0; i < 16; i++) {
                    int idx = tx + i * 256;          // 0..4095
                    int gg2 = idx >> 11;             // 0..1
                    int r   = (idx >> 5) & 63;
                    int k   = idx & 31;
                    HSX(gg2, r, k) = __ldcg(&hin[(long long)r * rs + gg2 * 256 + kk + k]);
                }
                __syncthreads();

                const int kb = kg * 256 + kk;
#pragma unroll
                for (int k = 0; k < 32; k++) {
                    float w0 = WS(colg * 2 + 0, kb + k);
                    float w1 = WS(colg * 2 + 1, kb + k);
#pragma unroll
                    for (int i = 0; i < 4; i++) {
                        float hv = HSX(kg, rowg * 4 + i, k);
                        acc[i][0] += hv * w0;
                        acc[i][1] += hv * w1;
                    }
                }
                __syncthreads();
            }
        }

        // K-split reduction: group 1 writes partials, group 0 adds + xp -> gates in ps
        if (kg == 1) {
#pragma unroll
            for (int i = 0; i < 4; i++)
#pragma unroll
                for (int j = 0; j < 2; j++)
                    ps[(rowg * 4 + i) * 16 + colg * 2 + j] = acc[i][j];
        }
        __syncthreads();
        if (kg == 0) {
#pragma unroll
            for (int i = 0; i < 4; i++) {
                int b = rowg * 4 + i;
                const float* xrow = xp + ((size_t)b * T_ + t) * G4_;
#pragma unroll
                for (int j = 0; j < 2; j++) {
                    int cc = colg * 2 + j;
                    int gg = cc >> 2;
                    int u  = cc & 3;
                    int o  = b * 16 + cc;
                    ps[o] = acc[i][j] + ps[o] + xrow[gg * H_ + j0 + u];
                }
            }
        }
        __syncthreads();

        // cell update: 256 cells (64 rows x 4 units), one per thread
        {
            int b = tx >> 2;
            int u = tx & 3;
            float gi = ps[b * 16 + 0 * 4 + u];
            float gf = ps[b * 16 + 1 * 4 + u];
            float gc = ps[b * 16 + 2 * 4 + u];
            float go = ps[b * 16 + 3 * 4 + u];
            float i_ = 1.f / (1.f + expf(-gi));
            float f_ = 1.f / (1.f + expf(-gf));
            float g_ = tanhf(gc);
            float o_ = 1.f / (1.f + expf(-go));
            float cold = (t == 0) ? 0.f : cs[tx];
            float cn = f_ * cold + i_ * g_;
            cs[tx] = cn;

            const long long outoff = (mode == 0) ? (long long)t * H_
                                                 : (long long)(t & 1) * B_ * H_;
            hbase[outoff + (long long)b * rs + j0 + u] = o_ * tanhf(cn);
        }

        // grid barrier (skip after last step)
        if (t < T_ - 1) {
            __syncthreads();
            if (tx == 0) {
                __threadfence();
                atomicAdd(&g_bar, 1u);
                unsigned target = (unsigned)(t + 1) * nblk;
                while (*((volatile unsigned int*)&g_bar) < target) { }
            }
            __syncthreads();
        }
    }
}

// ---------------------------------------------------------------------------
// Final FC: out[b,o] = h[b,:] . W_fc[o,:] + b_fc[o]
// ---------------------------------------------------------------------------
__global__ __launch_bounds__(128) void fc_kernel(
    const float* __restrict__ h, const float* __restrict__ Wfc,
    const float* __restrict__ bfc, float* __restrict__ out)
{
    __shared__ float hrow[H_];
    int b = blockIdx.x;
    for (int k = threadIdx.x; k < H_; k += 128) hrow[k] = h[b * H_ + k];
    __syncthreads();

    int o = threadIdx.x;
    float s = bfc[o];
    const float4* w4 = reinterpret_cast<const float4*>(Wfc + (size_t)o * H_);
    const float4* h4 = reinterpret_cast<const float4*>(hrow);
#pragma unroll 4
    for (int k = 0; k < H_ / 4; k++) {
        float4 w = w4[k];
        float4 hh = h4[k];
        s += w.x * hh.x + w.y * hh.y + w.z * hh.z + w.w * hh.w;
    }
    out[b * OUT_ + o] = s;
}

// ---------------------------------------------------------------------------
extern "C" void kernel_launch(void* const* d_in, const int* in_sizes, int n_in,
                              void* d_out, int out_size)
{
    const float* x     = (const float*)d_in[0];
    const float* W_ih0 = (const float*)d_in[1];
    const float* W_hh0 = (const float*)d_in[2];
    const float* b_ih0 = (const float*)d_in[3];
    const float* b_hh0 = (const float*)d_in[4];
    const float* W_ih1 = (const float*)d_in[5];
    const float* W_hh1 = (const float*)d_in[6];
    const float* b_ih1 = (const float*)d_in[7];
    const float* b_hh1 = (const float*)d_in[8];
    const float* W_fc  = (const float*)d_in[9];
    const float* b_fc  = (const float*)d_in[10];
    float* out = (float*)d_out;

    float *xp, *hseq, *h1;
    cudaGetSymbolAddress((void**)&xp,   g_xp);
    cudaGetSymbolAddress((void**)&hseq, g_hseq);
    cudaGetSymbolAddress((void**)&h1,   g_h1);

    const int smem_bytes = (16 * 514 + 2 * 64 * 33 + 1024 + 256) * 4;  // 54912
    cudaFuncSetAttribute(lstm_persist_kernel,
                         cudaFuncAttributeMaxDynamicSharedMemorySize, smem_bytes);

    const int M = B_ * T_;
    dim3 gemm_grid(G4_ / 128, M / 128);

    // Layer 0: xp = x @ W_ih0^T + b_ih0 + b_hh0, then persistent recurrence
    gemm_bias_kernel<<<gemm_grid, 256>>>(x, W_ih0, b_ih0, b_hh0, xp, M, G4_, IN_);
    bar_init_kernel<<<1, 1>>>();
    lstm_persist_kernel<<<NBLK, NTHR, smem_bytes>>>(xp, W_hh0, hseq, 0);

    // Layer 1: xp = hseq @ W_ih1^T + b_ih1 + b_hh1, then persistent recurrence
    gemm_bias_kernel<<<gemm_grid, 256>>>(hseq, W_ih1, b_ih1, b_hh1, xp, M, G4_, H_);
    bar_init_kernel<<<1, 1>>>();
    lstm_persist_kernel<<<NBLK, NTHR, smem_bytes>>>(xp, W_hh1, h1, 1);

    // Final FC on last hidden state (t=511 -> ping buffer 1)
    fc_kernel<<<B_, 128>>>(h1 + (size_t)B_ * H_, W_fc, b_fc, out);
}

// round 4
// speedup vs baseline: 1.1103x; 1.1103x over previous
#include <cuda_runtime.h>
#include <cuda_bf16.h>
#include <math.h>
#include <stdint.h>

#define B_   64
#define T_   512
#define IN_  128
#define H_   512
#define G4_  2048   // 4*H
#define OUT_ 128
#define M_   (B_ * T_)   // 32768

#define NBLK 128
#define NTHR 256

// ---------------- scratch (static device memory; no allocs) ----------------
__device__ float g_xp[(size_t)M_ * G4_];          // gate preactivations
__device__ float g_hseq[(size_t)M_ * H_];         // layer-0 hidden states
__device__ float g_h1[2][B_ * H_];                // layer-1 h ping-pong
__device__ unsigned int g_bar;                    // grid barrier counter

__device__ __nv_bfloat16 g_Ahi[(size_t)M_ * H_];  // A split (max K=512)
__device__ __nv_bfloat16 g_Alo[(size_t)M_ * H_];
__device__ __nv_bfloat16 g_Whi[(size_t)G4_ * H_];
__device__ __nv_bfloat16 g_Wlo[(size_t)G4_ * H_];

__global__ void bar_init_kernel() { g_bar = 0u; }

// ======================= helpers ==============================
__device__ __forceinline__ uint32_t smem_u32(const void* p) {
    uint32_t a;
    asm("{ .reg .u64 t; cvta.to.shared.u64 t, %1; cvt.u32.u64 %0, t; }"
        : "=r"(a) : "l"(p));
    return a;
}

#define LDSM_X4(r, addr) \
    asm volatile("ldmatrix.sync.aligned.m8n8.x4.shared.b16 {%0,%1,%2,%3}, [%4];" \
        : "=r"((r)[0]), "=r"((r)[1]), "=r"((r)[2]), "=r"((r)[3]) : "r"(addr))
#define LDSM_X2(r, addr) \
    asm volatile("ldmatrix.sync.aligned.m8n8.x2.shared.b16 {%0,%1}, [%2];" \
        : "=r"((r)[0]), "=r"((r)[1]) : "r"(addr))

__device__ __forceinline__ void mma16816(float* d, const uint32_t* a, const uint32_t* b) {
    asm volatile("mma.sync.aligned.m16n8k16.row.col.f32.bf16.bf16.f32 "
        "{%0,%1,%2,%3}, {%4,%5,%6,%7}, {%8,%9}, {%0,%1,%2,%3};"
        : "+f"(d[0]), "+f"(d[1]), "+f"(d[2]), "+f"(d[3])
        : "r"(a[0]), "r"(a[1]), "r"(a[2]), "r"(a[3]), "r"(b[0]), "r"(b[1]));
}

#define CP_ASYNC16(dst, src) \
    asm volatile("cp.async.cg.shared.global [%0], [%1], 16;" :: "r"(dst), "l"(src))
#define CP_COMMIT() asm volatile("cp.async.commit_group;" ::: "memory")
#define CP_WAIT(n)  asm volatile("cp.async.wait_group %0;" :: "n"(n) : "memory")

// ---------------------------------------------------------------------------
// fp32 -> (hi, lo) bf16 split
// ---------------------------------------------------------------------------
__global__ __launch_bounds__(256) void split_bf16_kernel(
    const float* __restrict__ in, __nv_bfloat16* __restrict__ hi,
    __nv_bfloat16* __restrict__ lo, int n)
{
    int i = blockIdx.x * 256 + threadIdx.x;
    if (i < n) {
        float v = in[i];
        __nv_bfloat16 h = __float2bfloat16(v);
        hi[i] = h;
        lo[i] = __float2bfloat16(v - __bfloat162float(h));
    }
}

// ---------------------------------------------------------------------------
// bf16x3 GEMM via mma.sync: C[M_,2048] = A[M_,K] @ W[2048,K]^T + b1 + b2
// CTA tile 128x128x32, 8 warps (2M x 4N), warp tile 64x32 (m16n8k16),
// cp.async double-buffered.
// ---------------------------------------------------------------------------
#define GSTRIDE 40                  // bf16 elems per smem row (80 B, LDSM conflict-free)
#define SMAT    (128 * GSTRIDE)     // one 128x32 matrix (padded), in elems
#define SSTAGE  (4 * SMAT)          // Ah, Al, Wh, Wl
#define GEMM_SMEM_BYTES (2 * SSTAGE * 2 + 128 * 4)

__global__ __launch_bounds__(256) void gemm_mma_kernel(
    const __nv_bfloat16* __restrict__ Ahi, const __nv_bfloat16* __restrict__ Alo,
    const __nv_bfloat16* __restrict__ Whi, const __nv_bfloat16* __restrict__ Wlo,
    const float* __restrict__ b1, const float* __restrict__ b2,
    float* __restrict__ C, int K)
{
    extern __shared__ __nv_bfloat16 sm[];
    float* biass = (float*)(sm + 2 * SSTAGE);

    const int tid  = threadIdx.x;
    const int wid  = tid >> 5;
    const int lane = tid & 31;
    const int wm   = wid >> 2;        // 0..1
    const int wn   = wid & 3;         // 0..3
    const int m0   = blockIdx.y * 128;
    const int n0   = blockIdx.x * 128;

    if (tid < 128) biass[tid] = b1[n0 + tid] + b2[n0 + tid];

    const int K8 = K >> 3;
    const uint4* gA[2] = { (const uint4*)Ahi, (const uint4*)Alo };
    const uint4* gW[2] = { (const uint4*)Whi, (const uint4*)Wlo };
    const uint32_t smb = smem_u32(sm);

    auto prefetch = [&](int kt, int st) {
        const int kk8 = kt * 4;                      // 32 bf16 = 4 uint4
        const uint32_t sbase = smb + (uint32_t)st * (SSTAGE * 2);
#pragma unroll
        for (int hl = 0; hl < 2; hl++) {
#pragma unroll
            for (int i = 0; i < 2; i++) {
                int idx = tid + i * 256;             // 0..511
                int r = idx >> 2, j = idx & 3;
                uint32_t dst = sbase + (uint32_t)(hl * SMAT + r * GSTRIDE) * 2 + j * 16;
                CP_ASYNC16(dst, gA[hl] + (size_t)(m0 + r) * K8 + kk8 + j);
            }
#pragma unroll
            for (int i = 0; i < 2; i++) {
                int idx = tid + i * 256;
                int r = idx >> 2, j = idx & 3;
                uint32_t dst = sbase + (uint32_t)((2 + hl) * SMAT + r * GSTRIDE) * 2 + j * 16;
                CP_ASYNC16(dst, gW[hl] + (size_t)(n0 + r) * K8 + kk8 + j);
            }
        }
        CP_COMMIT();
    };

    float acc[4][4][4];
#pragma unroll
    for (int mi = 0; mi < 4; mi++)
#pragma unroll
        for (int ni = 0; ni < 4; ni++)
#pragma unroll
            for (int e = 0; e < 4; e++) acc[mi][ni][e] = 0.f;

    const int KT = K / 32;
    prefetch(0, 0);

    for (int kt = 0; kt < KT; kt++) {
        if (kt + 1 < KT) { prefetch(kt + 1, (kt + 1) & 1); CP_WAIT(1); }
        else             { CP_WAIT(0); }
        __syncthreads();

        const uint32_t sbase = smb + (uint32_t)(kt & 1) * (SSTAGE * 2);
#pragma unroll
        for (int ks = 0; ks < 2; ks++) {
            uint32_t aH[4][4], aL[4][4], bH[4][2], bL[4][2];

            const int arow = wm * 64 + (lane & 7) + ((lane >> 3) & 1) * 8;
            const int acol = ks * 16 + (lane >> 4) * 8;
#pragma unroll
            for (int mi = 0; mi < 4; mi++) {
                uint32_t ad = sbase + (uint32_t)((arow + mi * 16) * GSTRIDE + acol) * 2;
                LDSM_X4(aH[mi], ad);
                LDSM_X4(aL[mi], ad + SMAT * 2);
            }
            const int l16  = lane & 15;
            const int brow = wn * 32 + (l16 & 7);
            const int bcol = ks * 16 + (l16 >> 3) * 8;
#pragma unroll
            for (int ni = 0; ni < 4; ni++) {
                uint32_t bd = sbase + (uint32_t)(2 * SMAT + (brow + ni * 8) * GSTRIDE + bcol) * 2;
                LDSM_X2(bH[ni], bd);
                LDSM_X2(bL[ni], bd + SMAT * 2);
            }
#pragma unroll
            for (int mi = 0; mi < 4; mi++)
#pragma unroll
                for (int ni = 0; ni < 4; ni++) {
                    mma16816(acc[mi][ni], aH[mi], bH[ni]);
                    mma16816(acc[mi][ni], aH[mi], bL[ni]);
                    mma16816(acc[mi][ni], aL[mi], bH[ni]);
                }
        }
        __syncthreads();
    }

    // epilogue: bias add + direct stores (float2 per fragment row)
#pragma unroll
    for (int mi = 0; mi < 4; mi++) {
        const int r0 = m0 + wm * 64 + mi * 16 + (lane >> 2);
#pragma unroll
        for (int ni = 0; ni < 4; ni++) {
            const int c = wn * 32 + ni * 8 + (lane & 3) * 2;
            float2 v0, v1;
            v0.x = acc[mi][ni][0] + biass[c];
            v0.y = acc[mi][ni][1] + biass[c + 1];
            v1.x = acc[mi][ni][2] + biass[c];
            v1.y = acc[mi][ni][3] + biass[c + 1];
            *(float2*)&C[(size_t)r0 * G4_ + n0 + c]       = v0;
            *(float2*)&C[(size_t)(r0 + 8) * G4_ + n0 + c] = v1;
        }
    }
}

// ---------------------------------------------------------------------------
// Persistent LSTM recurrence (unchanged from the passing R1 version)
// ---------------------------------------------------------------------------
#define WS(c,k)    ws[(c) * 514 + (k)]
#define HSX(g,r,k) hsm[((g) * 64 + (r)) * 33 + (k)]

__global__ __launch_bounds__(NTHR, 1) void lstm_persist_kernel(
    const float* __restrict__ xp, const float* __restrict__ Whh,
    float* __restrict__ hbase, int mode)
{
    extern __shared__ float smemf[];
    float* ws  = smemf;
    float* hsm = ws + 16 * 514;
    float* ps  = hsm + 2 * 64 * 33;
    float* cs  = ps + 1024;

    const int tx   = threadIdx.x;
    const int colg = tx & 7;
    const int rowg = (tx >> 3) & 15;
    const int kg   = tx >> 7;
    const int j0   = blockIdx.x * 4;

    const long long rs   = (mode == 0) ? (long long)T_ * H_ : (long long)H_;
    const unsigned  nblk = gridDim.x;

#pragma unroll
    for (int i = 0; i < 32; i++) {
        int idx = tx + i * 256;
        int cc  = idx >> 9;
        int k   = idx & 511;
        int gg  = cc >> 2;
        int u   = cc & 3;
        WS(cc, k) = Whh[(size_t)(gg * H_ + j0 + u) * H_ + k];
    }
    __syncthreads();

    for (int t = 0; t < T_; t++) {
        float acc[4][2];
#pragma unroll
        for (int i = 0; i < 4; i++) { acc[i][0] = 0.f; acc[i][1] = 0.f; }

        if (t > 0) {
            const long long inoff = (mode == 0) ? (long long)(t - 1) * H_
                                                : (long long)((t & 1) ^ 1) * B_ * H_;
            const float* hin = hbase + inoff;

            for (int kk = 0; kk < 256; kk += 32) {
#pragma unroll
                for (int i = 0; i < 16; i++) {
                    int idx = tx + i * 256;
                    int gg2 = idx >> 11;
                    int r   = (idx >> 5) & 63;
                    int k   = idx & 31;
                    HSX(gg2, r, k) = __ldcg(&hin[(long long)r * rs + gg2 * 256 + kk + k]);
                }
                __syncthreads();

                const int kb = kg * 256 + kk;
#pragma unroll
                for (int k = 0; k < 32; k++) {
                    float w0 = WS(colg * 2 + 0, kb + k);
                    float w1 = WS(colg * 2 + 1, kb + k);
#pragma unroll
                    for (int i = 0; i < 4; i++) {
                        float hv = HSX(kg, rowg * 4 + i, k);
                        acc[i][0] += hv * w0;
                        acc[i][1] += hv * w1;
                    }
                }
                __syncthreads();
            }
        }

        if (kg == 1) {
#pragma unroll
            for (int i = 0; i < 4; i++)
#pragma unroll
                for (int j = 0; j < 2; j++)
                    ps[(rowg * 4 + i) * 16 + colg * 2 + j] = acc[i][j];
        }
        __syncthreads();
        if (kg == 0) {
#pragma unroll
            for (int i = 0; i < 4; i++) {
                int b = rowg * 4 + i;
                const float* xrow = xp + ((size_t)b * T_ + t) * G4_;
#pragma unroll
                for (int j = 0; j < 2; j++) {
                    int cc = colg * 2 + j;
                    int gg = cc >> 2;
                    int u  = cc & 3;
                    int o  = b * 16 + cc;
                    ps[o] = acc[i][j] + ps[o] + xrow[gg * H_ + j0 + u];
                }
            }
        }
        __syncthreads();

        {
            int b = tx >> 2;
            int u = tx & 3;
            float gi = ps[b * 16 + 0 * 4 + u];
            float gf = ps[b * 16 + 1 * 4 + u];
            float gc = ps[b * 16 + 2 * 4 + u];
            float go = ps[b * 16 + 3 * 4 + u];
            float i_ = 1.f / (1.f + expf(-gi));
            float f_ = 1.f / (1.f + expf(-gf));
            float g_ = tanhf(gc);
            float o_ = 1.f / (1.f + expf(-go));
            float cold = (t == 0) ? 0.f : cs[tx];
            float cn = f_ * cold + i_ * g_;
            cs[tx] = cn;

            const long long outoff = (mode == 0) ? (long long)t * H_
                                                 : (long long)(t & 1) * B_ * H_;
            hbase[outoff + (long long)b * rs + j0 + u] = o_ * tanhf(cn);
        }

        if (t < T_ - 1) {
            __syncthreads();
            if (tx == 0) {
                __threadfence();
                atomicAdd(&g_bar, 1u);
                unsigned target = (unsigned)(t + 1) * nblk;
                while (*((volatile unsigned int*)&g_bar) < target) { }
            }
            __syncthreads();
        }
    }
}

// ---------------------------------------------------------------------------
// Final FC
// ---------------------------------------------------------------------------
__global__ __launch_bounds__(128) void fc_kernel(
    const float* __restrict__ h, const float* __restrict__ Wfc,
    const float* __restrict__ bfc, float* __restrict__ out)
{
    __shared__ float hrow[H_];
    int b = blockIdx.x;
    for (int k = threadIdx.x; k < H_; k += 128) hrow[k] = h[b * H_ + k];
    __syncthreads();

    int o = threadIdx.x;
    float s = bfc[o];
    const float4* w4 = reinterpret_cast<const float4*>(Wfc + (size_t)o * H_);
    const float4* h4 = reinterpret_cast<const float4*>(hrow);
#pragma unroll 4
    for (int k = 0; k < H_ / 4; k++) {
        float4 w = w4[k];
        float4 hh = h4[k];
        s += w.x * hh.x + w.y * hh.y + w.z * hh.z + w.w * hh.w;
    }
    out[b * OUT_ + o] = s;
}

// ---------------------------------------------------------------------------
extern "C" void kernel_launch(void* const* d_in, const int* in_sizes, int n_in,
                              void* d_out, int out_size)
{
    const float* x     = (const float*)d_in[0];
    const float* W_ih0 = (const float*)d_in[1];
    const float* W_hh0 = (const float*)d_in[2];
    const float* b_ih0 = (const float*)d_in[3];
    const float* b_hh0 = (const float*)d_in[4];
    const float* W_ih1 = (const float*)d_in[5];
    const float* W_hh1 = (const float*)d_in[6];
    const float* b_ih1 = (const float*)d_in[7];
    const float* b_hh1 = (const float*)d_in[8];
    const float* W_fc  = (const float*)d_in[9];
    const float* b_fc  = (const float*)d_in[10];
    float* out = (float*)d_out;

    float *xp, *hseq, *h1;
    __nv_bfloat16 *ahi, *alo, *whi, *wlo;
    cudaGetSymbolAddress((void**)&xp,   g_xp);
    cudaGetSymbolAddress((void**)&hseq, g_hseq);
    cudaGetSymbolAddress((void**)&h1,   g_h1);
    cudaGetSymbolAddress((void**)&ahi,  g_Ahi);
    cudaGetSymbolAddress((void**)&alo,  g_Alo);
    cudaGetSymbolAddress((void**)&whi,  g_Whi);
    cudaGetSymbolAddress((void**)&wlo,  g_Wlo);

    const int lstm_smem = (16 * 514 + 2 * 64 * 33 + 1024 + 256) * 4;
    cudaFuncSetAttribute(lstm_persist_kernel,
                         cudaFuncAttributeMaxDynamicSharedMemorySize, lstm_smem);
    cudaFuncSetAttribute(gemm_mma_kernel,
                         cudaFuncAttributeMaxDynamicSharedMemorySize, GEMM_SMEM_BYTES);

    dim3 mma_grid(G4_ / 128, M_ / 128);   // (16, 256)

    // ---- Layer 0 ----
    {
        int nA = M_ * IN_;
        int nW = G4_ * IN_;
        split_bf16_kernel<<<(nA + 255) / 256, 256>>>(x, ahi, alo, nA);
        split_bf16_kernel<<<(nW + 255) / 256, 256>>>(W_ih0, whi, wlo, nW);
        gemm_mma_kernel<<<mma_grid, 256, GEMM_SMEM_BYTES>>>(ahi, alo, whi, wlo,
                                                            b_ih0, b_hh0, xp, IN_);
    }
    bar_init_kernel<<<1, 1>>>();
    lstm_persist_kernel<<<NBLK, NTHR, lstm_smem>>>(xp, W_hh0, hseq, 0);

    // ---- Layer 1 ----
    {
        int nA = M_ * H_;
        int nW = G4_ * H_;
        split_bf16_kernel<<<(nA + 255) / 256, 256>>>(hseq, ahi, alo, nA);
        split_bf16_kernel<<<(nW + 255) / 256, 256>>>(W_ih1, whi, wlo, nW);
        gemm_mma_kernel<<<mma_grid, 256, GEMM_SMEM_BYTES>>>(ahi, alo, whi, wlo,
                                                            b_ih1, b_hh1, xp, H_);
    }
    bar_init_kernel<<<1, 1>>>();
    lstm_persist_kernel<<<NBLK, NTHR, lstm_smem>>>(xp, W_hh1, h1, 1);

    fc_kernel<<<B_, 128>>>(h1 + (size_t)B_ * H_, W_fc, b_fc, out);
}

// round 5
// speedup vs baseline: 1.7731x; 1.5970x over previous
#include <cuda_runtime.h>
#include <cuda_bf16.h>
#include <math.h>
#include <stdint.h>

#define B_   64
#define T_   512
#define IN_  128
#define H_   512
#define G4_  2048   // 4*H
#define OUT_ 128
#define M_   (B_ * T_)   // 32768

#define RBLK 64     // recurrence blocks (persistent, co-resident)
#define RTHR 256

// ---------------- scratch (static device memory; no allocs) ----------------
__device__ float g_xp[(size_t)M_ * G4_];            // gate preactivations
__device__ unsigned int g_bar;                      // grid barrier counter

__device__ __nv_bfloat16 g_Ahi[(size_t)M_ * H_];    // layer-1 GEMM A / layer-0 h (hi)
__device__ __nv_bfloat16 g_Alo[(size_t)M_ * H_];    // (lo)
__device__ __nv_bfloat16 g_Xhi[(size_t)M_ * IN_];   // x split
__device__ __nv_bfloat16 g_Xlo[(size_t)M_ * IN_];
__device__ __nv_bfloat16 g_Whi[(size_t)G4_ * H_];   // W_ih split
__device__ __nv_bfloat16 g_Wlo[(size_t)G4_ * H_];
__device__ __nv_bfloat16 g_h1hi[2 * B_ * H_];       // layer-1 h ping-pong (hi)
__device__ __nv_bfloat16 g_h1lo[2 * B_ * H_];       // (lo)

__global__ void bar_init_kernel() { g_bar = 0u; }

// ======================= helpers ==============================
__device__ __forceinline__ uint32_t smem_u32(const void* p) {
    uint32_t a;
    asm("{ .reg .u64 t; cvta.to.shared.u64 t, %1; cvt.u32.u64 %0, t; }"
        : "=r"(a) : "l"(p));
    return a;
}

#define LDSM_X4(r, addr) \
    asm volatile("ldmatrix.sync.aligned.m8n8.x4.shared.b16 {%0,%1,%2,%3}, [%4];" \
        : "=r"((r)[0]), "=r"((r)[1]), "=r"((r)[2]), "=r"((r)[3]) : "r"(addr))
#define LDSM_X2(r, addr) \
    asm volatile("ldmatrix.sync.aligned.m8n8.x2.shared.b16 {%0,%1}, [%2];" \
        : "=r"((r)[0]), "=r"((r)[1]) : "r"(addr))

__device__ __forceinline__ void mma16816(float* d, const uint32_t* a, const uint32_t* b) {
    asm volatile("mma.sync.aligned.m16n8k16.row.col.f32.bf16.bf16.f32 "
        "{%0,%1,%2,%3}, {%4,%5,%6,%7}, {%8,%9}, {%0,%1,%2,%3};"
        : "+f"(d[0]), "+f"(d[1]), "+f"(d[2]), "+f"(d[3])
        : "r"(a[0]), "r"(a[1]), "r"(a[2]), "r"(a[3]), "r"(b[0]), "r"(b[1]));
}

#define CP_ASYNC16(dst, src) \
    asm volatile("cp.async.cg.shared.global [%0], [%1], 16;" :: "r"(dst), "l"(src))
#define CP_COMMIT() asm volatile("cp.async.commit_group;" ::: "memory")
#define CP_WAIT(n)  asm volatile("cp.async.wait_group %0;" :: "n"(n) : "memory")

// ---------------------------------------------------------------------------
// fp32 -> (hi, lo) bf16 split
// ---------------------------------------------------------------------------
__global__ __launch_bounds__(256) void split_bf16_kernel(
    const float* __restrict__ in, __nv_bfloat16* __restrict__ hi,
    __nv_bfloat16* __restrict__ lo, int n)
{
    int i = blockIdx.x * 256 + threadIdx.x;
    if (i < n) {
        float v = in[i];
        __nv_bfloat16 h = __float2bfloat16(v);
        hi[i] = h;
        lo[i] = __float2bfloat16(v - __bfloat162float(h));
    }
}

// ---------------------------------------------------------------------------
// bf16x3 GEMM via mma.sync (unchanged from passing R3 version)
// ---------------------------------------------------------------------------
#define GSTRIDE 40
#define SMAT    (128 * GSTRIDE)
#define SSTAGE  (4 * SMAT)
#define GEMM_SMEM_BYTES (2 * SSTAGE * 2 + 128 * 4)

__global__ __launch_bounds__(256) void gemm_mma_kernel(
    const __nv_bfloat16* __restrict__ Ahi, const __nv_bfloat16* __restrict__ Alo,
    const __nv_bfloat16* __restrict__ Whi, const __nv_bfloat16* __restrict__ Wlo,
    const float* __restrict__ b1, const float* __restrict__ b2,
    float* __restrict__ C, int K)
{
    extern __shared__ __nv_bfloat16 sm[];
    float* biass = (float*)(sm + 2 * SSTAGE);

    const int tid  = threadIdx.x;
    const int wid  = tid >> 5;
    const int lane = tid & 31;
    const int wm   = wid >> 2;
    const int wn   = wid & 3;
    const int m0   = blockIdx.y * 128;
    const int n0   = blockIdx.x * 128;

    if (tid < 128) biass[tid] = b1[n0 + tid] + b2[n0 + tid];

    const int K8 = K >> 3;
    const uint4* gA[2] = { (const uint4*)Ahi, (const uint4*)Alo };
    const uint4* gW[2] = { (const uint4*)Whi, (const uint4*)Wlo };
    const uint32_t smb = smem_u32(sm);

    auto prefetch = [&](int kt, int st) {
        const int kk8 = kt * 4;
        const uint32_t sbase = smb + (uint32_t)st * (SSTAGE * 2);
#pragma unroll
        for (int hl = 0; hl < 2; hl++) {
#pragma unroll
            for (int i = 0; i < 2; i++) {
                int idx = tid + i * 256;
                int r = idx >> 2, j = idx & 3;
                uint32_t dst = sbase + (uint32_t)(hl * SMAT + r * GSTRIDE) * 2 + j * 16;
                CP_ASYNC16(dst, gA[hl] + (size_t)(m0 + r) * K8 + kk8 + j);
            }
#pragma unroll
            for (int i = 0; i < 2; i++) {
                int idx = tid + i * 256;
                int r = idx >> 2, j = idx & 3;
                uint32_t dst = sbase + (uint32_t)((2 + hl) * SMAT + r * GSTRIDE) * 2 + j * 16;
                CP_ASYNC16(dst, gW[hl] + (size_t)(n0 + r) * K8 + kk8 + j);
            }
        }
        CP_COMMIT();
    };

    float acc[4][4][4];
#pragma unroll
    for (int mi = 0; mi < 4; mi++)
#pragma unroll
        for (int ni = 0; ni < 4; ni++)
#pragma unroll
            for (int e = 0; e < 4; e++) acc[mi][ni][e] = 0.f;

    const int KT = K / 32;
    prefetch(0, 0);

    for (int kt = 0; kt < KT; kt++) {
        if (kt + 1 < KT) { prefetch(kt + 1, (kt + 1) & 1); CP_WAIT(1); }
        else             { CP_WAIT(0); }
        __syncthreads();

        const uint32_t sbase = smb + (uint32_t)(kt & 1) * (SSTAGE * 2);
#pragma unroll
        for (int ks = 0; ks < 2; ks++) {
            uint32_t aH[4][4], aL[4][4], bH[4][2], bL[4][2];

            const int arow = wm * 64 + (lane & 7) + ((lane >> 3) & 1) * 8;
            const int acol = ks * 16 + (lane >> 4) * 8;
#pragma unroll
            for (int mi = 0; mi < 4; mi++) {
                uint32_t ad = sbase + (uint32_t)((arow + mi * 16) * GSTRIDE + acol) * 2;
                LDSM_X4(aH[mi], ad);
                LDSM_X4(aL[mi], ad + SMAT * 2);
            }
            const int l16  = lane & 15;
            const int brow = wn * 32 + (l16 & 7);
            const int bcol = ks * 16 + (l16 >> 3) * 8;
#pragma unroll
            for (int ni = 0; ni < 4; ni++) {
                uint32_t bd = sbase + (uint32_t)(2 * SMAT + (brow + ni * 8) * GSTRIDE + bcol) * 2;
                LDSM_X2(bH[ni], bd);
                LDSM_X2(bL[ni], bd + SMAT * 2);
            }
#pragma unroll
            for (int mi = 0; mi < 4; mi++)
#pragma unroll
                for (int ni = 0; ni < 4; ni++) {
                    mma16816(acc[mi][ni], aH[mi], bH[ni]);
                    mma16816(acc[mi][ni], aH[mi], bL[ni]);
                    mma16816(acc[mi][ni], aL[mi], bH[ni]);
                }
        }
        __syncthreads();
    }

#pragma unroll
    for (int mi = 0; mi < 4; mi++) {
        const int r0 = m0 + wm * 64 + mi * 16 + (lane >> 2);
#pragma unroll
        for (int ni = 0; ni < 4; ni++) {
            const int c = wn * 32 + ni * 8 + (lane & 3) * 2;
            float2 v0, v1;
            v0.x = acc[mi][ni][0] + biass[c];
            v0.y = acc[mi][ni][1] + biass[c + 1];
            v1.x = acc[mi][ni][2] + biass[c];
            v1.y = acc[mi][ni][3] + biass[c + 1];
            *(float2*)&C[(size_t)r0 * G4_ + n0 + c]       = v0;
            *(float2*)&C[(size_t)(r0 + 8) * G4_ + n0 + c] = v1;
        }
    }
}

// ---------------------------------------------------------------------------
// Tensor-core persistent LSTM recurrence.
// 64 blocks x 256 threads. Block owns 8 hidden units (32 gate cols).
// W_hh slice split to bf16 hi/lo in SMEM (resident across all steps).
// h stored globally as bf16 hi/lo pair; staged per step via cp.async pipeline.
// Warp (mw,nw): mw=wid>>1 (M16 of 64), nw=wid&1 (N16 of 32).
// mode 0: h rows at (b*T+t)*H (layer 0, feeds layer-1 GEMM directly)
// mode 1: h ping-pong [2][B][H]
// ---------------------------------------------------------------------------
#define WS_MATB   33280u   // 32*520*2
#define HS_MATB   9216u    // 64*72*2
#define HS_BUFB   18432u   // hi+lo
#define XS_OFF    103424u  // 2*WS_MATB + 2*HS_BUFB
#define GS_OFF    111616u
#define CS_OFF    120064u
#define LSTM_SMEM 122112

__global__ __launch_bounds__(RTHR, 1) void lstm_mma_kernel(
    const float* __restrict__ xp, const float* __restrict__ Whh,
    __nv_bfloat16* __restrict__ hhi, __nv_bfloat16* __restrict__ hlo,
    int mode, unsigned bar_base)
{
    extern __shared__ char sm8[];
    __nv_bfloat16* ws = (__nv_bfloat16*)sm8;
    float* xs = (float*)(sm8 + XS_OFF);   // [64][32]
    float* gs = (float*)(sm8 + GS_OFF);   // [64][33]
    float* cs = (float*)(sm8 + CS_OFF);   // [512]

    const int tx   = threadIdx.x;
    const int wid  = tx >> 5;
    const int lane = tx & 31;
    const int l16  = lane & 15;
    const int mw   = wid >> 1;           // 0..3
    const int nw   = wid & 1;            // 0..1
    const int j0   = blockIdx.x * 8;
    const long long rs = (mode == 0) ? (long long)T_ * H_ : (long long)H_;

    // load + split W slice: ws[cc][k], cc = gg*8+u -> Whh row gg*512 + j0 + u
#pragma unroll 4
    for (int i = 0; i < 64; i++) {
        int idx = tx + i * 256;          // 0..16383
        int cc = idx >> 9, k = idx & 511;
        int gg = cc >> 3, u = cc & 7;
        float w = Whh[(size_t)(gg * H_ + j0 + u) * H_ + k];
        __nv_bfloat16 wh = __float2bfloat16(w);
        ws[cc * 520 + k] = wh;
        ws[32 * 520 + cc * 520 + k] = __float2bfloat16(w - __bfloat162float(wh));
    }
    __syncthreads();

    const uint32_t smb = smem_u32(sm8);
    const uint32_t wsb = smb;
    const uint32_t hsb = smb + 2 * WS_MATB;

    for (int t = 0; t < T_; t++) {
        // issue xp tile group: xs[b][gg*8+u]
#pragma unroll
        for (int i = 0; i < 2; i++) {
            int idx = tx + i * 256;
            int b = idx >> 3, gg = (idx >> 1) & 3, seg = idx & 1;
            uint32_t dst = smb + XS_OFF + (uint32_t)(b * 32 + gg * 8 + seg * 4) * 4;
            CP_ASYNC16(dst, xp + ((size_t)b * T_ + t) * G4_ + gg * H_ + j0 + seg * 4);
        }
        CP_COMMIT();

        float acc[2][4] = {};
        if (t > 0) {
            const long long inoff = (mode == 0) ? (long long)(t - 1) * H_
                                                : (long long)((t & 1) ^ 1) * B_ * H_;
            auto issue = [&](int c) {
#pragma unroll
                for (int i = 0; i < 4; i++) {
                    int idx = tx + i * 256;          // 0..1023
                    int mat = idx >> 9;              // 0=hi 1=lo
                    int r   = (idx >> 3) & 63;
                    int seg = idx & 7;
                    const __nv_bfloat16* src =
                        (mat ? hlo : hhi) + inoff + (long long)r * rs + c * 64 + seg * 8;
                    uint32_t dst = hsb + (uint32_t)(c & 1) * HS_BUFB
                                 + (uint32_t)mat * HS_MATB
                                 + (uint32_t)(r * 72 + seg * 8) * 2;
                    CP_ASYNC16(dst, src);
                }
                CP_COMMIT();
            };
            issue(0);
            for (int c = 0; c < 8; c++) {
                if (c < 7) { issue(c + 1); CP_WAIT(1); }
                else       { CP_WAIT(0); }
                __syncthreads();
                const uint32_t hb = hsb + (uint32_t)(c & 1) * HS_BUFB;
#pragma unroll
                for (int kk2 = 0; kk2 < 4; kk2++) {
                    uint32_t aH[4], aL[4];
                    int arow = mw * 16 + (lane & 7) + ((lane >> 3) & 1) * 8;
                    int acol = kk2 * 16 + (lane >> 4) * 8;
                    uint32_t ad = hb + (uint32_t)(arow * 72 + acol) * 2;
                    LDSM_X4(aH, ad);
                    LDSM_X4(aL, ad + HS_MATB);
                    int kg = c * 4 + kk2;
#pragma unroll
                    for (int ni = 0; ni < 2; ni++) {
                        uint32_t bH[2], bL[2];
                        int brow = nw * 16 + ni * 8 + (l16 & 7);
                        int bcol = kg * 16 + (l16 >> 3) * 8;
                        uint32_t bd = wsb + (uint32_t)(brow * 520 + bcol) * 2;
                        LDSM_X2(bH, bd);
                        LDSM_X2(bL, bd + WS_MATB);
                        mma16816(acc[ni], aH, bH);
                        mma16816(acc[ni], aH, bL);
                        mma16816(acc[ni], aL, bH);
                    }
                }
                __syncthreads();
            }
            // stage gate matmul results: gs[batch][col]
#pragma unroll
            for (int ni = 0; ni < 2; ni++) {
                int r = mw * 16 + (lane >> 2);
                int cb = nw * 16 + ni * 8 + (lane & 3) * 2;
                gs[r * 33 + cb]           = acc[ni][0];
                gs[r * 33 + cb + 1]       = acc[ni][1];
                gs[(r + 8) * 33 + cb]     = acc[ni][2];
                gs[(r + 8) * 33 + cb + 1] = acc[ni][3];
            }
        } else {
            CP_WAIT(0);
        }
        __syncthreads();

        // cell update: 512 cells (64 batches x 8 units), 2 per thread
        const long long outoff = (mode == 0) ? (long long)t * H_
                                             : (long long)(t & 1) * B_ * H_;
#pragma unroll
        for (int i = 0; i < 2; i++) {
            int e = tx + i * 256;
            int b = e >> 3, u = e & 7;
            float gi = xs[b * 32 + 0 * 8 + u];
            float gf = xs[b * 32 + 1 * 8 + u];
            float gc = xs[b * 32 + 2 * 8 + u];
            float go = xs[b * 32 + 3 * 8 + u];
            if (t > 0) {
                gi += gs[b * 33 + 0 * 8 + u];
                gf += gs[b * 33 + 1 * 8 + u];
                gc += gs[b * 33 + 2 * 8 + u];
                go += gs[b * 33 + 3 * 8 + u];
            }
            float i_ = 1.f / (1.f + expf(-gi));
            float f_ = 1.f / (1.f + expf(-gf));
            float g_ = tanhf(gc);
            float o_ = 1.f / (1.f + expf(-go));
            float cold = (t == 0) ? 0.f : cs[e];
            float cn = f_ * cold + i_ * g_;
            cs[e] = cn;
            float h = o_ * tanhf(cn);
            __nv_bfloat16 hh = __float2bfloat16(h);
            __nv_bfloat16 hl = __float2bfloat16(h - __bfloat162float(hh));
            hhi[outoff + (long long)b * rs + j0 + u] = hh;
            hlo[outoff + (long long)b * rs + j0 + u] = hl;
        }

        if (t < T_ - 1) {
            __syncthreads();
            if (tx == 0) {
                __threadfence();
                atomicAdd(&g_bar, 1u);
                unsigned target = bar_base + (unsigned)(t + 1) * gridDim.x;
                while (*((volatile unsigned int*)&g_bar) < target) { }
                __threadfence();
            }
            __syncthreads();
        }
    }
}

// ---------------------------------------------------------------------------
// Final FC: h reconstructed from bf16 hi/lo pair
// ---------------------------------------------------------------------------
__global__ __launch_bounds__(128) void fc_kernel(
    const __nv_bfloat16* __restrict__ hhi, const __nv_bfloat16* __restrict__ hlo,
    const float* __restrict__ Wfc, const float* __restrict__ bfc,
    float* __restrict__ out)
{
    __shared__ float hrow[H_];
    int b = blockIdx.x;
    for (int k = threadIdx.x; k < H_; k += 128)
        hrow[k] = __bfloat162float(hhi[b * H_ + k]) + __bfloat162float(hlo[b * H_ + k]);
    __syncthreads();

    int o = threadIdx.x;
    float s = bfc[o];
    const float4* w4 = reinterpret_cast<const float4*>(Wfc + (size_t)o * H_);
    const float4* h4 = reinterpret_cast<const float4*>(hrow);
#pragma unroll 4
    for (int k = 0; k < H_ / 4; k++) {
        float4 w = w4[k];
        float4 hh = h4[k];
        s += w.x * hh.x + w.y * hh.y + w.z * hh.z + w.w * hh.w;
    }
    out[b * OUT_ + o] = s;
}

// ---------------------------------------------------------------------------
extern "C" void kernel_launch(void* const* d_in, const int* in_sizes, int n_in,
                              void* d_out, int out_size)
{
    const float* x     = (const float*)d_in[0];
    const float* W_ih0 = (const float*)d_in[1];
    const float* W_hh0 = (const float*)d_in[2];
    const float* b_ih0 = (const float*)d_in[3];
    const float* b_hh0 = (const float*)d_in[4];
    const float* W_ih1 = (const float*)d_in[5];
    const float* W_hh1 = (const float*)d_in[6];
    const float* b_ih1 = (const float*)d_in[7];
    const float* b_hh1 = (const float*)d_in[8];
    const float* W_fc  = (const float*)d_in[9];
    const float* b_fc  = (const float*)d_in[10];
    float* out = (float*)d_out;

    float* xp;
    __nv_bfloat16 *ahi, *alo, *xhi, *xlo, *whi, *wlo, *h1hi, *h1lo;
    cudaGetSymbolAddress((void**)&xp,   g_xp);
    cudaGetSymbolAddress((void**)&ahi,  g_Ahi);
    cudaGetSymbolAddress((void**)&alo,  g_Alo);
    cudaGetSymbolAddress((void**)&xhi,  g_Xhi);
    cudaGetSymbolAddress((void**)&xlo,  g_Xlo);
    cudaGetSymbolAddress((void**)&whi,  g_Whi);
    cudaGetSymbolAddress((void**)&wlo,  g_Wlo);
    cudaGetSymbolAddress((void**)&h1hi, g_h1hi);
    cudaGetSymbolAddress((void**)&h1lo, g_h1lo);

    cudaFuncSetAttribute(gemm_mma_kernel,
                         cudaFuncAttributeMaxDynamicSharedMemorySize, GEMM_SMEM_BYTES);
    cudaFuncSetAttribute(lstm_mma_kernel,
                         cudaFuncAttributeMaxDynamicSharedMemorySize, LSTM_SMEM);

    dim3 mma_grid(G4_ / 128, M_ / 128);   // (16, 256)

    // ---- Layer 0 ----
    {
        int nA = M_ * IN_;
        int nW = G4_ * IN_;
        split_bf16_kernel<<<(nA + 255) / 256, 256>>>(x, xhi, xlo, nA);
        split_bf16_kernel<<<(nW + 255) / 256, 256>>>(W_ih0, whi, wlo, nW);
        gemm_mma_kernel<<<mma_grid, 256, GEMM_SMEM_BYTES>>>(xhi, xlo, whi, wlo,
                                                            b_ih0, b_hh0, xp, IN_);
    }
    bar_init_kernel<<<1, 1>>>();
    lstm_mma_kernel<<<RBLK, RTHR, LSTM_SMEM>>>(xp, W_hh0, ahi, alo, 0, 0u);

    // ---- Layer 1 (A split produced directly by layer-0 recurrence) ----
    {
        int nW = G4_ * H_;
        split_bf16_kernel<<<(nW + 255) / 256, 256>>>(W_ih1, whi, wlo, nW);
        gemm_mma_kernel<<<mma_grid, 256, GEMM_SMEM_BYTES>>>(ahi, alo, whi, wlo,
                                                            b_ih1, b_hh1, xp, H_);
    }
    lstm_mma_kernel<<<RBLK, RTHR, LSTM_SMEM>>>(xp, W_hh1, h1hi, h1lo, 1,
                                               (unsigned)(T_ - 1) * RBLK);

    fc_kernel<<<B_, 128>>>(h1hi + (size_t)B_ * H_, h1lo + (size_t)B_ * H_,
                           W_fc, b_fc, out);
}

// round 6
// speedup vs baseline: 1.9547x; 1.1024x over previous
#include <cuda_runtime.h>
#include <cuda_bf16.h>
#include <math.h>
#include <stdint.h>

#define B_   64
#define T_   512
#define IN_  128
#define H_   512
#define G4_  2048   // 4*H
#define OUT_ 128
#define M_   (B_ * T_)   // 32768

#define RBLK 64     // recurrence blocks (persistent, co-resident)
#define RTHR 256

// ---------------- scratch (static device memory; no allocs) ----------------
__device__ float g_xp[(size_t)M_ * G4_];            // gate preactivations
__device__ unsigned int g_bar;                      // grid barrier counter

__device__ __nv_bfloat16 g_Ahi[(size_t)M_ * H_];    // layer-1 GEMM A / layer-0 h (hi)
__device__ __nv_bfloat16 g_Alo[(size_t)M_ * H_];    // (lo)
__device__ __nv_bfloat16 g_Xhi[(size_t)M_ * IN_];   // x split
__device__ __nv_bfloat16 g_Xlo[(size_t)M_ * IN_];
__device__ __nv_bfloat16 g_Whi[(size_t)G4_ * H_];   // W_ih split
__device__ __nv_bfloat16 g_Wlo[(size_t)G4_ * H_];
__device__ __nv_bfloat16 g_h1hi[2 * B_ * H_];       // layer-1 h ping-pong (hi)
__device__ __nv_bfloat16 g_h1lo[2 * B_ * H_];       // (lo)

__global__ void bar_init_kernel() { g_bar = 0u; }

// ======================= helpers ==============================
__device__ __forceinline__ uint32_t smem_u32(const void* p) {
    uint32_t a;
    asm("{ .reg .u64 t; cvta.to.shared.u64 t, %1; cvt.u32.u64 %0, t; }"
        : "=r"(a) : "l"(p));
    return a;
}

#define LDSM_X4(r, addr) \
    asm volatile("ldmatrix.sync.aligned.m8n8.x4.shared.b16 {%0,%1,%2,%3}, [%4];" \
        : "=r"((r)[0]), "=r"((r)[1]), "=r"((r)[2]), "=r"((r)[3]) : "r"(addr))
#define LDSM_X2(r, addr) \
    asm volatile("ldmatrix.sync.aligned.m8n8.x2.shared.b16 {%0,%1}, [%2];" \
        : "=r"((r)[0]), "=r"((r)[1]) : "r"(addr))

__device__ __forceinline__ void mma16816(float* d, const uint32_t* a, const uint32_t* b) {
    asm volatile("mma.sync.aligned.m16n8k16.row.col.f32.bf16.bf16.f32 "
        "{%0,%1,%2,%3}, {%4,%5,%6,%7}, {%8,%9}, {%0,%1,%2,%3};"
        : "+f"(d[0]), "+f"(d[1]), "+f"(d[2]), "+f"(d[3])
        : "r"(a[0]), "r"(a[1]), "r"(a[2]), "r"(a[3]), "r"(b[0]), "r"(b[1]));
}

#define CP_ASYNC16(dst, src) \
    asm volatile("cp.async.cg.shared.global [%0], [%1], 16;" :: "r"(dst), "l"(src))
#define CP_COMMIT() asm volatile("cp.async.commit_group;" ::: "memory")
#define CP_WAIT(n)  asm volatile("cp.async.wait_group %0;" :: "n"(n) : "memory")

// ---------------------------------------------------------------------------
// fp32 -> (hi, lo) bf16 split
// ---------------------------------------------------------------------------
__global__ __launch_bounds__(256) void split_bf16_kernel(
    const float* __restrict__ in, __nv_bfloat16* __restrict__ hi,
    __nv_bfloat16* __restrict__ lo, int n)
{
    int i = blockIdx.x * 256 + threadIdx.x;
    if (i < n) {
        float v = in[i];
        __nv_bfloat16 h = __float2bfloat16(v);
        hi[i] = h;
        lo[i] = __float2bfloat16(v - __bfloat162float(h));
    }
}

// ---------------------------------------------------------------------------
// bf16x3 GEMM via mma.sync (unchanged, passing since R3)
// ---------------------------------------------------------------------------
#define GSTRIDE 40
#define SMAT    (128 * GSTRIDE)
#define SSTAGE  (4 * SMAT)
#define GEMM_SMEM_BYTES (2 * SSTAGE * 2 + 128 * 4)

__global__ __launch_bounds__(256) void gemm_mma_kernel(
    const __nv_bfloat16* __restrict__ Ahi, const __nv_bfloat16* __restrict__ Alo,
    const __nv_bfloat16* __restrict__ Whi, const __nv_bfloat16* __restrict__ Wlo,
    const float* __restrict__ b1, const float* __restrict__ b2,
    float* __restrict__ C, int K)
{
    extern __shared__ __nv_bfloat16 sm[];
    float* biass = (float*)(sm + 2 * SSTAGE);

    const int tid  = threadIdx.x;
    const int wid  = tid >> 5;
    const int lane = tid & 31;
    const int wm   = wid >> 2;
    const int wn   = wid & 3;
    const int m0   = blockIdx.y * 128;
    const int n0   = blockIdx.x * 128;

    if (tid < 128) biass[tid] = b1[n0 + tid] + b2[n0 + tid];

    const int K8 = K >> 3;
    const uint4* gA[2] = { (const uint4*)Ahi, (const uint4*)Alo };
    const uint4* gW[2] = { (const uint4*)Whi, (const uint4*)Wlo };
    const uint32_t smb = smem_u32(sm);

    auto prefetch = [&](int kt, int st) {
        const int kk8 = kt * 4;
        const uint32_t sbase = smb + (uint32_t)st * (SSTAGE * 2);
#pragma unroll
        for (int hl = 0; hl < 2; hl++) {
#pragma unroll
            for (int i = 0; i < 2; i++) {
                int idx = tid + i * 256;
                int r = idx >> 2, j = idx & 3;
                uint32_t dst = sbase + (uint32_t)(hl * SMAT + r * GSTRIDE) * 2 + j * 16;
                CP_ASYNC16(dst, gA[hl] + (size_t)(m0 + r) * K8 + kk8 + j);
            }
#pragma unroll
            for (int i = 0; i < 2; i++) {
                int idx = tid + i * 256;
                int r = idx >> 2, j = idx & 3;
                uint32_t dst = sbase + (uint32_t)((2 + hl) * SMAT + r * GSTRIDE) * 2 + j * 16;
                CP_ASYNC16(dst, gW[hl] + (size_t)(n0 + r) * K8 + kk8 + j);
            }
        }
        CP_COMMIT();
    };

    float acc[4][4][4];
#pragma unroll
    for (int mi = 0; mi < 4; mi++)
#pragma unroll
        for (int ni = 0; ni < 4; ni++)
#pragma unroll
            for (int e = 0; e < 4; e++) acc[mi][ni][e] = 0.f;

    const int KT = K / 32;
    prefetch(0, 0);

    for (int kt = 0; kt < KT; kt++) {
        if (kt + 1 < KT) { prefetch(kt + 1, (kt + 1) & 1); CP_WAIT(1); }
        else             { CP_WAIT(0); }
        __syncthreads();

        const uint32_t sbase = smb + (uint32_t)(kt & 1) * (SSTAGE * 2);
#pragma unroll
        for (int ks = 0; ks < 2; ks++) {
            uint32_t aH[4][4], aL[4][4], bH[4][2], bL[4][2];

            const int arow = wm * 64 + (lane & 7) + ((lane >> 3) & 1) * 8;
            const int acol = ks * 16 + (lane >> 4) * 8;
#pragma unroll
            for (int mi = 0; mi < 4; mi++) {
                uint32_t ad = sbase + (uint32_t)((arow + mi * 16) * GSTRIDE + acol) * 2;
                LDSM_X4(aH[mi], ad);
                LDSM_X4(aL[mi], ad + SMAT * 2);
            }
            const int l16  = lane & 15;
            const int brow = wn * 32 + (l16 & 7);
            const int bcol = ks * 16 + (l16 >> 3) * 8;
#pragma unroll
            for (int ni = 0; ni < 4; ni++) {
                uint32_t bd = sbase + (uint32_t)(2 * SMAT + (brow + ni * 8) * GSTRIDE + bcol) * 2;
                LDSM_X2(bH[ni], bd);
                LDSM_X2(bL[ni], bd + SMAT * 2);
            }
#pragma unroll
            for (int mi = 0; mi < 4; mi++)
#pragma unroll
                for (int ni = 0; ni < 4; ni++) {
                    mma16816(acc[mi][ni], aH[mi], bH[ni]);
                    mma16816(acc[mi][ni], aH[mi], bL[ni]);
                    mma16816(acc[mi][ni], aL[mi], bH[ni]);
                }
        }
        __syncthreads();
    }

#pragma unroll
    for (int mi = 0; mi < 4; mi++) {
        const int r0 = m0 + wm * 64 + mi * 16 + (lane >> 2);
#pragma unroll
        for (int ni = 0; ni < 4; ni++) {
            const int c = wn * 32 + ni * 8 + (lane & 3) * 2;
            float2 v0, v1;
            v0.x = acc[mi][ni][0] + biass[c];
            v0.y = acc[mi][ni][1] + biass[c + 1];
            v1.x = acc[mi][ni][2] + biass[c];
            v1.y = acc[mi][ni][3] + biass[c + 1];
            *(float2*)&C[(size_t)r0 * G4_ + n0 + c]       = v0;
            *(float2*)&C[(size_t)(r0 + 8) * G4_ + n0 + c] = v1;
        }
    }
}

// ---------------------------------------------------------------------------
// Tensor-core persistent LSTM recurrence, low-latency step version.
// 64 blocks x 256 threads, block owns 8 hidden units (32 gate cols).
// All 4 K=128 chunks of h staged in SMEM per step (no WAR reuse inside a
// step), one syncthreads per chunk, 6 independent HMMA accumulator chains,
// release/acquire grid barrier.
// ---------------------------------------------------------------------------
#define WS_MATB   33280u            // 32*520*2
#define HS_OFF    66560u            // 2*WS_MATB
#define HC_MATB   17408u            // 64*136*2
#define HC_BYTES  34816u            // hi+lo per chunk
#define XS_OFF    205824u           // HS_OFF + 4*HC_BYTES
#define GS_OFF    214016u
#define CS_OFF    222464u
#define LSTM_SMEM 224512

__global__ __launch_bounds__(RTHR, 1) void lstm_mma_kernel(
    const float* __restrict__ xp, const float* __restrict__ Whh,
    __nv_bfloat16* __restrict__ hhi, __nv_bfloat16* __restrict__ hlo,
    int mode, unsigned bar_base, unsigned* __restrict__ bar)
{
    extern __shared__ char sm8[];
    __nv_bfloat16* ws = (__nv_bfloat16*)sm8;
    float* xs = (float*)(sm8 + XS_OFF);   // [64][32]
    float* gs = (float*)(sm8 + GS_OFF);   // [64][33]
    float* cs = (float*)(sm8 + CS_OFF);   // [512]

    const int tx   = threadIdx.x;
    const int wid  = tx >> 5;
    const int lane = tx & 31;
    const int l16  = lane & 15;
    const int mw   = wid >> 1;           // 0..3
    const int nw   = wid & 1;            // 0..1
    const int j0   = blockIdx.x * 8;
    const long long rs = (mode == 0) ? (long long)T_ * H_ : (long long)H_;

    // load + split W slice: ws[cc][k], cc = gg*8+u -> Whh row gg*512 + j0 + u
#pragma unroll 4
    for (int i = 0; i < 64; i++) {
        int idx = tx + i * 256;
        int cc = idx >> 9, k = idx & 511;
        int gg = cc >> 3, u = cc & 7;
        float w = Whh[(size_t)(gg * H_ + j0 + u) * H_ + k];
        __nv_bfloat16 wh = __float2bfloat16(w);
        ws[cc * 520 + k] = wh;
        ws[16640 + cc * 520 + k] = __float2bfloat16(w - __bfloat162float(wh));
    }
    __syncthreads();

    const uint32_t smb = smem_u32(sm8);
    const uint32_t wsb = smb;
    const uint32_t hsb = smb + HS_OFF;

    float accA[2][4], accB1[2][4], accB2[2][4];

    for (int t = 0; t < T_; t++) {
        // group 0: xp tile -> xs[b][gg*8+u]
#pragma unroll
        for (int i = 0; i < 2; i++) {
            int idx = tx + i * 256;
            int b = idx >> 3, gg = (idx >> 1) & 3, seg = idx & 1;
            uint32_t dst = smb + XS_OFF + (uint32_t)(b * 32 + gg * 8 + seg * 4) * 4;
            CP_ASYNC16(dst, xp + ((size_t)b * T_ + t) * G4_ + gg * H_ + j0 + seg * 4);
        }
        CP_COMMIT();

#pragma unroll
        for (int ni = 0; ni < 2; ni++)
#pragma unroll
            for (int e = 0; e < 4; e++) {
                accA[ni][e] = 0.f; accB1[ni][e] = 0.f; accB2[ni][e] = 0.f;
            }

        if (t > 0) {
            const long long inoff = (mode == 0) ? (long long)(t - 1) * H_
                                                : (long long)((t & 1) ^ 1) * B_ * H_;
            // groups 1..4: all four K=128 chunks of h (hi+lo)
#pragma unroll
            for (int c = 0; c < 4; c++) {
#pragma unroll
                for (int i = 0; i < 8; i++) {
                    int idx = tx + i * 256;          // 0..2047
                    int mat = idx >> 10;             // 0=hi 1=lo
                    int r   = (idx >> 4) & 63;
                    int seg = idx & 15;
                    const __nv_bfloat16* src =
                        (mat ? hlo : hhi) + inoff + (long long)r * rs + c * 128 + seg * 8;
                    uint32_t dst = hsb + (uint32_t)c * HC_BYTES
                                 + (uint32_t)mat * HC_MATB
                                 + (uint32_t)(r * 136 + seg * 8) * 2;
                    CP_ASYNC16(dst, src);
                }
                CP_COMMIT();
            }

            auto consume = [&](int c) {
                const uint32_t hb = hsb + (uint32_t)c * HC_BYTES;
#pragma unroll
                for (int kk2 = 0; kk2 < 8; kk2++) {
                    uint32_t aH[4], aL[4];
                    int arow = mw * 16 + (lane & 7) + ((lane >> 3) & 1) * 8;
                    int acol = kk2 * 16 + (lane >> 4) * 8;
                    uint32_t ad = hb + (uint32_t)(arow * 136 + acol) * 2;
                    LDSM_X4(aH, ad);
                    LDSM_X4(aL, ad + HC_MATB);
                    int kg = c * 8 + kk2;
#pragma unroll
                    for (int ni = 0; ni < 2; ni++) {
                        uint32_t bH[2], bL[2];
                        int brow = nw * 16 + ni * 8 + (l16 & 7);
                        int bcol = kg * 16 + (l16 >> 3) * 8;
                        uint32_t bd = wsb + (uint32_t)(brow * 520 + bcol) * 2;
                        LDSM_X2(bH, bd);
                        LDSM_X2(bL, bd + WS_MATB);
                        mma16816(accA[ni],  aH, bH);
                        mma16816(accB1[ni], aH, bL);
                        mma16816(accB2[ni], aL, bH);
                    }
                }
            };
            CP_WAIT(3); __syncthreads(); consume(0);
            CP_WAIT(2); __syncthreads(); consume(1);
            CP_WAIT(1); __syncthreads(); consume(2);
            CP_WAIT(0); __syncthreads(); consume(3);

            // stage gate matmul results: gs[batch][col]
#pragma unroll
            for (int ni = 0; ni < 2; ni++) {
                int r = mw * 16 + (lane >> 2);
                int cb = nw * 16 + ni * 8 + (lane & 3) * 2;
                gs[r * 33 + cb]           = accA[ni][0] + accB1[ni][0] + accB2[ni][0];
                gs[r * 33 + cb + 1]       = accA[ni][1] + accB1[ni][1] + accB2[ni][1];
                gs[(r + 8) * 33 + cb]     = accA[ni][2] + accB1[ni][2] + accB2[ni][2];
                gs[(r + 8) * 33 + cb + 1] = accA[ni][3] + accB1[ni][3] + accB2[ni][3];
            }
        } else {
            CP_WAIT(0);
        }
        __syncthreads();

        // cell update: 512 cells, 2 per thread
        const long long outoff = (mode == 0) ? (long long)t * H_
                                             : (long long)(t & 1) * B_ * H_;
#pragma unroll
        for (int i = 0; i < 2; i++) {
            int e = tx + i * 256;
            int b = e >> 3, u = e & 7;
            float gi = xs[b * 32 + 0 * 8 + u];
            float gf = xs[b * 32 + 1 * 8 + u];
            float gc = xs[b * 32 + 2 * 8 + u];
            float go = xs[b * 32 + 3 * 8 + u];
            if (t > 0) {
                gi += gs[b * 33 + 0 * 8 + u];
                gf += gs[b * 33 + 1 * 8 + u];
                gc += gs[b * 33 + 2 * 8 + u];
                go += gs[b * 33 + 3 * 8 + u];
            }
            float i_ = 1.f / (1.f + expf(-gi));
            float f_ = 1.f / (1.f + expf(-gf));
            float g_ = tanhf(gc);
            float o_ = 1.f / (1.f + expf(-go));
            float cold = (t == 0) ? 0.f : cs[e];
            float cn = f_ * cold + i_ * g_;
            cs[e] = cn;
            float h = o_ * tanhf(cn);
            __nv_bfloat16 hh = __float2bfloat16(h);
            __nv_bfloat16 hl = __float2bfloat16(h - __bfloat162float(hh));
            hhi[outoff + (long long)b * rs + j0 + u] = hh;
            hlo[outoff + (long long)b * rs + j0 + u] = hl;
        }

        // grid barrier: release-add, acquire-poll
        if (t < T_ - 1) {
            __syncthreads();
            if (tx == 0) {
                unsigned target = bar_base + (unsigned)(t + 1) * gridDim.x;
                asm volatile("red.release.gpu.global.add.u32 [%0], %1;"
                             :: "l"(bar), "r"(1u) : "memory");
                unsigned v;
                do {
                    asm volatile("ld.acquire.gpu.global.u32 %0, [%1];"
                                 : "=r"(v) : "l"(bar) : "memory");
                } while (v < target);
            }
            __syncthreads();
        }
    }
}

// ---------------------------------------------------------------------------
// Final FC: h reconstructed from bf16 hi/lo pair
// ---------------------------------------------------------------------------
__global__ __launch_bounds__(128) void fc_kernel(
    const __nv_bfloat16* __restrict__ hhi, const __nv_bfloat16* __restrict__ hlo,
    const float* __restrict__ Wfc, const float* __restrict__ bfc,
    float* __restrict__ out)
{
    __shared__ float hrow[H_];
    int b = blockIdx.x;
    for (int k = threadIdx.x; k < H_; k += 128)
        hrow[k] = __bfloat162float(hhi[b * H_ + k]) + __bfloat162float(hlo[b * H_ + k]);
    __syncthreads();

    int o = threadIdx.x;
    float s = bfc[o];
    const float4* w4 = reinterpret_cast<const float4*>(Wfc + (size_t)o * H_);
    const float4* h4 = reinterpret_cast<const float4*>(hrow);
#pragma unroll 4
    for (int k = 0; k < H_ / 4; k++) {
        float4 w = w4[k];
        float4 hh = h4[k];
        s += w.x * hh.x + w.y * hh.y + w.z * hh.z + w.w * hh.w;
    }
    out[b * OUT_ + o] = s;
}

// ---------------------------------------------------------------------------
extern "C" void kernel_launch(void* const* d_in, const int* in_sizes, int n_in,
                              void* d_out, int out_size)
{
    const float* x     = (const float*)d_in[0];
    const float* W_ih0 = (const float*)d_in[1];
    const float* W_hh0 = (const float*)d_in[2];
    const float* b_ih0 = (const float*)d_in[3];
    const float* b_hh0 = (const float*)d_in[4];
    const float* W_ih1 = (const float*)d_in[5];
    const float* W_hh1 = (const float*)d_in[6];
    const float* b_ih1 = (const float*)d_in[7];
    const float* b_hh1 = (const float*)d_in[8];
    const float* W_fc  = (const float*)d_in[9];
    const float* b_fc  = (const float*)d_in[10];
    float* out = (float*)d_out;

    float* xp;
    unsigned* bar;
    __nv_bfloat16 *ahi, *alo, *xhi, *xlo, *whi, *wlo, *h1hi, *h1lo;
    cudaGetSymbolAddress((void**)&xp,   g_xp);
    cudaGetSymbolAddress((void**)&bar,  g_bar);
    cudaGetSymbolAddress((void**)&ahi,  g_Ahi);
    cudaGetSymbolAddress((void**)&alo,  g_Alo);
    cudaGetSymbolAddress((void**)&xhi,  g_Xhi);
    cudaGetSymbolAddress((void**)&xlo,  g_Xlo);
    cudaGetSymbolAddress((void**)&whi,  g_Whi);
    cudaGetSymbolAddress((void**)&wlo,  g_Wlo);
    cudaGetSymbolAddress((void**)&h1hi, g_h1hi);
    cudaGetSymbolAddress((void**)&h1lo, g_h1lo);

    cudaFuncSetAttribute(gemm_mma_kernel,
                         cudaFuncAttributeMaxDynamicSharedMemorySize, GEMM_SMEM_BYTES);
    cudaFuncSetAttribute(lstm_mma_kernel,
                         cudaFuncAttributeMaxDynamicSharedMemorySize, LSTM_SMEM);

    dim3 mma_grid(G4_ / 128, M_ / 128);   // (16, 256)

    // ---- Layer 0 ----
    {
        int nA = M_ * IN_;
        int nW = G4_ * IN_;
        split_bf16_kernel<<<(nA + 255) / 256, 256>>>(x, xhi, xlo, nA);
        split_bf16_kernel<<<(nW + 255) / 256, 256>>>(W_ih0, whi, wlo, nW);
        gemm_mma_kernel<<<mma_grid, 256, GEMM_SMEM_BYTES>>>(xhi, xlo, whi, wlo,
                                                            b_ih0, b_hh0, xp, IN_);
    }
    bar_init_kernel<<<1, 1>>>();
    lstm_mma_kernel<<<RBLK, RTHR, LSTM_SMEM>>>(xp, W_hh0, ahi, alo, 0, 0u, bar);

    // ---- Layer 1 (A split produced directly by layer-0 recurrence) ----
    {
        int nW = G4_ * H_;
        split_bf16_kernel<<<(nW + 255) / 256, 256>>>(W_ih1, whi, wlo, nW);
        gemm_mma_kernel<<<mma_grid, 256, GEMM_SMEM_BYTES>>>(ahi, alo, whi, wlo,
                                                            b_ih1, b_hh1, xp, H_);
    }
    lstm_mma_kernel<<<RBLK, RTHR, LSTM_SMEM>>>(xp, W_hh1, h1hi, h1lo, 1,
                                               (unsigned)(T_ - 1) * RBLK, bar);

    fc_kernel<<<B_, 128>>>(h1hi + (size_t)B_ * H_, h1lo + (size_t)B_ * H_,
                           W_fc, b_fc, out);
}

// round 7
// speedup vs baseline: 2.4405x; 1.2485x over previous
#include <cuda_runtime.h>
#include <cuda_bf16.h>
#include <math.h>
#include <stdint.h>

#define B_   64
#define T_   512
#define IN_  128
#define H_   512
#define G4_  2048   // 4*H
#define OUT_ 128
#define M_   (B_ * T_)   // 32768

#define FBLK 128    // fused grid: 64 layer-0 + 64 layer-1 blocks
#define RTHR 256

// ---------------- scratch (static device memory; no allocs) ----------------
__device__ float g_xp[(size_t)M_ * G4_];            // layer-0 gate preactivations
__device__ unsigned int g_bar;                      // grid barrier counter

__device__ __nv_bfloat16 g_Xhi[(size_t)M_ * IN_];   // x split
__device__ __nv_bfloat16 g_Xlo[(size_t)M_ * IN_];
__device__ __nv_bfloat16 g_Whi[(size_t)G4_ * IN_];  // W_ih0 split
__device__ __nv_bfloat16 g_Wlo[(size_t)G4_ * IN_];
__device__ __nv_bfloat16 g_h0hi[2 * B_ * H_];       // layer-0 h ping-pong
__device__ __nv_bfloat16 g_h0lo[2 * B_ * H_];
__device__ __nv_bfloat16 g_h1hi[2 * B_ * H_];       // layer-1 h ping-pong
__device__ __nv_bfloat16 g_h1lo[2 * B_ * H_];

__global__ void bar_init_kernel() { g_bar = 0u; }

// ======================= helpers ==============================
__device__ __forceinline__ uint32_t smem_u32(const void* p) {
    uint32_t a;
    asm("{ .reg .u64 t; cvta.to.shared.u64 t, %1; cvt.u32.u64 %0, t; }"
        : "=r"(a) : "l"(p));
    return a;
}

#define LDSM_X4(r, addr) \
    asm volatile("ldmatrix.sync.aligned.m8n8.x4.shared.b16 {%0,%1,%2,%3}, [%4];" \
        : "=r"((r)[0]), "=r"((r)[1]), "=r"((r)[2]), "=r"((r)[3]) : "r"(addr))
#define LDSM_X2(r, addr) \
    asm volatile("ldmatrix.sync.aligned.m8n8.x2.shared.b16 {%0,%1}, [%2];" \
        : "=r"((r)[0]), "=r"((r)[1]) : "r"(addr))

__device__ __forceinline__ void mma16816(float* d, const uint32_t* a, const uint32_t* b) {
    asm volatile("mma.sync.aligned.m16n8k16.row.col.f32.bf16.bf16.f32 "
        "{%0,%1,%2,%3}, {%4,%5,%6,%7}, {%8,%9}, {%0,%1,%2,%3};"
        : "+f"(d[0]), "+f"(d[1]), "+f"(d[2]), "+f"(d[3])
        : "r"(a[0]), "r"(a[1]), "r"(a[2]), "r"(a[3]), "r"(b[0]), "r"(b[1]));
}

#define CP_ASYNC16(dst, src) \
    asm volatile("cp.async.cg.shared.global [%0], [%1], 16;" :: "r"(dst), "l"(src))
#define CP_COMMIT() asm volatile("cp.async.commit_group;" ::: "memory")
#define CP_WAIT(n)  asm volatile("cp.async.wait_group %0;" :: "n"(n) : "memory")

// ---------------------------------------------------------------------------
// fp32 -> (hi, lo) bf16 split
// ---------------------------------------------------------------------------
__global__ __launch_bounds__(256) void split_bf16_kernel(
    const float* __restrict__ in, __nv_bfloat16* __restrict__ hi,
    __nv_bfloat16* __restrict__ lo, int n)
{
    int i = blockIdx.x * 256 + threadIdx.x;
    if (i < n) {
        float v = in[i];
        __nv_bfloat16 h = __float2bfloat16(v);
        hi[i] = h;
        lo[i] = __float2bfloat16(v - __bfloat162float(h));
    }
}

// ---------------------------------------------------------------------------
// bf16x3 GEMM via mma.sync (layer-0 xp only; unchanged, passing since R3)
// ---------------------------------------------------------------------------
#define GSTRIDE 40
#define SMAT    (128 * GSTRIDE)
#define SSTAGE  (4 * SMAT)
#define GEMM_SMEM_BYTES (2 * SSTAGE * 2 + 128 * 4)

__global__ __launch_bounds__(256) void gemm_mma_kernel(
    const __nv_bfloat16* __restrict__ Ahi, const __nv_bfloat16* __restrict__ Alo,
    const __nv_bfloat16* __restrict__ Whi, const __nv_bfloat16* __restrict__ Wlo,
    const float* __restrict__ b1, const float* __restrict__ b2,
    float* __restrict__ C, int K)
{
    extern __shared__ __nv_bfloat16 sm[];
    float* biass = (float*)(sm + 2 * SSTAGE);

    const int tid  = threadIdx.x;
    const int wid  = tid >> 5;
    const int lane = tid & 31;
    const int wm   = wid >> 2;
    const int wn   = wid & 3;
    const int m0   = blockIdx.y * 128;
    const int n0   = blockIdx.x * 128;

    if (tid < 128) biass[tid] = b1[n0 + tid] + b2[n0 + tid];

    const int K8 = K >> 3;
    const uint4* gA[2] = { (const uint4*)Ahi, (const uint4*)Alo };
    const uint4* gW[2] = { (const uint4*)Whi, (const uint4*)Wlo };
    const uint32_t smb = smem_u32(sm);

    auto prefetch = [&](int kt, int st) {
        const int kk8 = kt * 4;
        const uint32_t sbase = smb + (uint32_t)st * (SSTAGE * 2);
#pragma unroll
        for (int hl = 0; hl < 2; hl++) {
#pragma unroll
            for (int i = 0; i < 2; i++) {
                int idx = tid + i * 256;
                int r = idx >> 2, j = idx & 3;
                uint32_t dst = sbase + (uint32_t)(hl * SMAT + r * GSTRIDE) * 2 + j * 16;
                CP_ASYNC16(dst, gA[hl] + (size_t)(m0 + r) * K8 + kk8 + j);
            }
#pragma unroll
            for (int i = 0; i < 2; i++) {
                int idx = tid + i * 256;
                int r = idx >> 2, j = idx & 3;
                uint32_t dst = sbase + (uint32_t)((2 + hl) * SMAT + r * GSTRIDE) * 2 + j * 16;
                CP_ASYNC16(dst, gW[hl] + (size_t)(n0 + r) * K8 + kk8 + j);
            }
        }
        CP_COMMIT();
    };

    float acc[4][4][4];
#pragma unroll
    for (int mi = 0; mi < 4; mi++)
#pragma unroll
        for (int ni = 0; ni < 4; ni++)
#pragma unroll
            for (int e = 0; e < 4; e++) acc[mi][ni][e] = 0.f;

    const int KT = K / 32;
    prefetch(0, 0);

    for (int kt = 0; kt < KT; kt++) {
        if (kt + 1 < KT) { prefetch(kt + 1, (kt + 1) & 1); CP_WAIT(1); }
        else             { CP_WAIT(0); }
        __syncthreads();

        const uint32_t sbase = smb + (uint32_t)(kt & 1) * (SSTAGE * 2);
#pragma unroll
        for (int ks = 0; ks < 2; ks++) {
            uint32_t aH[4][4], aL[4][4], bH[4][2], bL[4][2];

            const int arow = wm * 64 + (lane & 7) + ((lane >> 3) & 1) * 8;
            const int acol = ks * 16 + (lane >> 4) * 8;
#pragma unroll
            for (int mi = 0; mi < 4; mi++) {
                uint32_t ad = sbase + (uint32_t)((arow + mi * 16) * GSTRIDE + acol) * 2;
                LDSM_X4(aH[mi], ad);
                LDSM_X4(aL[mi], ad + SMAT * 2);
            }
            const int l16  = lane & 15;
            const int brow = wn * 32 + (l16 & 7);
            const int bcol = ks * 16 + (l16 >> 3) * 8;
#pragma unroll
            for (int ni = 0; ni < 4; ni++) {
                uint32_t bd = sbase + (uint32_t)(2 * SMAT + (brow + ni * 8) * GSTRIDE + bcol) * 2;
                LDSM_X2(bH[ni], bd);
                LDSM_X2(bL[ni], bd + SMAT * 2);
            }
#pragma unroll
            for (int mi = 0; mi < 4; mi++)
#pragma unroll
                for (int ni = 0; ni < 4; ni++) {
                    mma16816(acc[mi][ni], aH[mi], bH[ni]);
                    mma16816(acc[mi][ni], aH[mi], bL[ni]);
                    mma16816(acc[mi][ni], aL[mi], bH[ni]);
                }
        }
        __syncthreads();
    }

#pragma unroll
    for (int mi = 0; mi < 4; mi++) {
        const int r0 = m0 + wm * 64 + mi * 16 + (lane >> 2);
#pragma unroll
        for (int ni = 0; ni < 4; ni++) {
            const int c = wn * 32 + ni * 8 + (lane & 3) * 2;
            float2 v0, v1;
            v0.x = acc[mi][ni][0] + biass[c];
            v0.y = acc[mi][ni][1] + biass[c + 1];
            v1.x = acc[mi][ni][2] + biass[c];
            v1.y = acc[mi][ni][3] + biass[c + 1];
            *(float2*)&C[(size_t)r0 * G4_ + n0 + c]       = v0;
            *(float2*)&C[(size_t)(r0 + 8) * G4_ + n0 + c] = v1;
        }
    }
}

// ---------------------------------------------------------------------------
// FUSED two-layer persistent LSTM. 128 blocks x 256 threads.
// Blocks 0..63  : layer 0, unit slice j0 (K=512 vs h0[t-1]), xp from g_xp.
// Blocks 64..127: layer 1, unit slice j0 (K=1024 vs [h0[t] ; h1[t-1]]),
//                 weight = [W_ih1 ; W_hh1] slice resident in SMEM.
// Pipeline: stage s: L0 computes h0[s], L1 computes h1[s-1]. 513 stages,
// one grid barrier per stage.
// ---------------------------------------------------------------------------
// layer-0 SMEM layout (same as R6 proven kernel)
#define WS0_MATB  33280u            // 32*520*2
#define HS0_OFF   66560u
#define HC_MATB   17408u            // 64*136*2
#define HC_BYTES  34816u            // hi+lo per chunk
#define XS0_OFF   205824u           // HS0_OFF + 4*HC_BYTES
#define GS0_OFF   214016u
#define CS0_OFF   222464u
// layer-1 SMEM layout
#define WS1_STR   1048              // elems per col row (2096 B; conflict-free LDSM)
#define WS1_MATB  67072u            // 32*1048*2
#define HS1_OFF   134144u           // 2 chunk buffers
#define GS1_OFF   203776u
#define CS1_OFF   212224u
#define BS1_OFF   214272u
#define FUSED_SMEM 224512

__global__ __launch_bounds__(RTHR, 1) void lstm_fused_kernel(
    const float* __restrict__ xp0, const float* __restrict__ Whh0,
    const float* __restrict__ Wih1, const float* __restrict__ Whh1,
    const float* __restrict__ b_ih1, const float* __restrict__ b_hh1,
    __nv_bfloat16* __restrict__ h0hi, __nv_bfloat16* __restrict__ h0lo,
    __nv_bfloat16* __restrict__ h1hi, __nv_bfloat16* __restrict__ h1lo,
    unsigned* __restrict__ bar)
{
    extern __shared__ char sm8[];
    const int tx   = threadIdx.x;
    const int wid  = tx >> 5;
    const int lane = tx & 31;
    const int l16  = lane & 31 & 15;
    const int mw   = wid >> 1;           // 0..3
    const int nw   = wid & 1;            // 0..1
    const bool isL0 = blockIdx.x < 64;
    const int j0   = (blockIdx.x & 63) * 8;

    const uint32_t smb = smem_u32(sm8);
    __nv_bfloat16* ws = (__nv_bfloat16*)sm8;

    if (isL0) {
        // ---- layer-0 setup: split W_hh0 slice into SMEM (stride 520) ----
#pragma unroll 4
        for (int i = 0; i < 64; i++) {
            int idx = tx + i * 256;
            int cc = idx >> 9, k = idx & 511;
            int gg = cc >> 3, u = cc & 7;
            float w = Whh0[(size_t)(gg * H_ + j0 + u) * H_ + k];
            __nv_bfloat16 wh = __float2bfloat16(w);
            ws[cc * 520 + k] = wh;
            ws[16640 + cc * 520 + k] = __float2bfloat16(w - __bfloat162float(wh));
        }
    } else {
        // ---- layer-1 setup: split [W_ih1 ; W_hh1] slice (stride 1048) ----
#pragma unroll 4
        for (int i = 0; i < 128; i++) {
            int idx = tx + i * 256;          // 0..32767
            int cc = idx >> 10, k = idx & 1023;
            int gg = cc >> 3, u = cc & 7;
            size_t row = (size_t)(gg * H_ + j0 + u) * H_;
            float w = (k < 512) ? Wih1[row + k] : Whh1[row + k - 512];
            __nv_bfloat16 wh = __float2bfloat16(w);
            ws[cc * WS1_STR + k] = wh;
            ws[33536 + cc * WS1_STR + k] = __float2bfloat16(w - __bfloat162float(wh));
        }
        if (tx < 32) {
            int gg = tx >> 3, u = tx & 7;
            ((float*)(sm8 + BS1_OFF))[tx] =
                b_ih1[gg * H_ + j0 + u] + b_hh1[gg * H_ + j0 + u];
        }
    }
    __syncthreads();

    float accA[2][4], accB1[2][4], accB2[2][4];

    for (int s = 0; s <= T_; s++) {
        if (isL0 && s < T_) {
            // ================= layer-0 step s =================
            const int t = s;
            float* xs = (float*)(sm8 + XS0_OFF);
            float* gs = (float*)(sm8 + GS0_OFF);
            float* cs = (float*)(sm8 + CS0_OFF);
            const uint32_t hsb = smb + HS0_OFF;

            // group 0: xp tile
#pragma unroll
            for (int i = 0; i < 2; i++) {
                int idx = tx + i * 256;
                int b = idx >> 3, gg = (idx >> 1) & 3, seg = idx & 1;
                uint32_t dst = smb + XS0_OFF + (uint32_t)(b * 32 + gg * 8 + seg * 4) * 4;
                CP_ASYNC16(dst, xp0 + ((size_t)b * T_ + t) * G4_ + gg * H_ + j0 + seg * 4);
            }
            CP_COMMIT();

#pragma unroll
            for (int ni = 0; ni < 2; ni++)
#pragma unroll
                for (int e = 0; e < 4; e++) {
                    accA[ni][e] = 0.f; accB1[ni][e] = 0.f; accB2[ni][e] = 0.f;
                }

            if (t > 0) {
                const long long inoff = (long long)((t & 1) ^ 1) * B_ * H_;
#pragma unroll
                for (int c = 0; c < 4; c++) {
#pragma unroll
                    for (int i = 0; i < 8; i++) {
                        int idx = tx + i * 256;
                        int mat = idx >> 10;
                        int r   = (idx >> 4) & 63;
                        int seg = idx & 15;
                        const __nv_bfloat16* src =
                            (mat ? h0lo : h0hi) + inoff + (long long)r * H_ + c * 128 + seg * 8;
                        uint32_t dst = hsb + (uint32_t)c * HC_BYTES
                                     + (uint32_t)mat * HC_MATB
                                     + (uint32_t)(r * 136 + seg * 8) * 2;
                        CP_ASYNC16(dst, src);
                    }
                    CP_COMMIT();
                }

                auto consume = [&](int c) {
                    const uint32_t hb = hsb + (uint32_t)c * HC_BYTES;
#pragma unroll
                    for (int kk2 = 0; kk2 < 8; kk2++) {
                        uint32_t aH[4], aL[4];
                        int arow = mw * 16 + (lane & 7) + ((lane >> 3) & 1) * 8;
                        int acol = kk2 * 16 + (lane >> 4) * 8;
                        uint32_t ad = hb + (uint32_t)(arow * 136 + acol) * 2;
                        LDSM_X4(aH, ad);
                        LDSM_X4(aL, ad + HC_MATB);
                        int kg = c * 8 + kk2;
#pragma unroll
                        for (int ni = 0; ni < 2; ni++) {
                            uint32_t bH[2], bL[2];
                            int brow = nw * 16 + ni * 8 + (l16 & 7);
                            int bcol = kg * 16 + (l16 >> 3) * 8;
                            uint32_t bd = smb + (uint32_t)(brow * 520 + bcol) * 2;
                            LDSM_X2(bH, bd);
                            LDSM_X2(bL, bd + WS0_MATB);
                            mma16816(accA[ni],  aH, bH);
                            mma16816(accB1[ni], aH, bL);
                            mma16816(accB2[ni], aL, bH);
                        }
                    }
                };
                CP_WAIT(3); __syncthreads(); consume(0);
                CP_WAIT(2); __syncthreads(); consume(1);
                CP_WAIT(1); __syncthreads(); consume(2);
                CP_WAIT(0); __syncthreads(); consume(3);

#pragma unroll
                for (int ni = 0; ni < 2; ni++) {
                    int r = mw * 16 + (lane >> 2);
                    int cb = nw * 16 + ni * 8 + (lane & 3) * 2;
                    gs[r * 33 + cb]           = accA[ni][0] + accB1[ni][0] + accB2[ni][0];
                    gs[r * 33 + cb + 1]       = accA[ni][1] + accB1[ni][1] + accB2[ni][1];
                    gs[(r + 8) * 33 + cb]     = accA[ni][2] + accB1[ni][2] + accB2[ni][2];
                    gs[(r + 8) * 33 + cb + 1] = accA[ni][3] + accB1[ni][3] + accB2[ni][3];
                }
            } else {
                CP_WAIT(0);
            }
            __syncthreads();

            const long long outoff = (long long)(t & 1) * B_ * H_;
#pragma unroll
            for (int i = 0; i < 2; i++) {
                int e = tx + i * 256;
                int b = e >> 3, u = e & 7;
                float gi = xs[b * 32 + 0 * 8 + u];
                float gf = xs[b * 32 + 1 * 8 + u];
                float gc = xs[b * 32 + 2 * 8 + u];
                float go = xs[b * 32 + 3 * 8 + u];
                if (t > 0) {
                    gi += gs[b * 33 + 0 * 8 + u];
                    gf += gs[b * 33 + 1 * 8 + u];
                    gc += gs[b * 33 + 2 * 8 + u];
                    go += gs[b * 33 + 3 * 8 + u];
                }
                float i_ = 1.f / (1.f + expf(-gi));
                float f_ = 1.f / (1.f + expf(-gf));
                float g_ = tanhf(gc);
                float o_ = 1.f / (1.f + expf(-go));
                float cold = (t == 0) ? 0.f : cs[e];
                float cn = f_ * cold + i_ * g_;
                cs[e] = cn;
                float h = o_ * tanhf(cn);
                __nv_bfloat16 hh = __float2bfloat16(h);
                __nv_bfloat16 hl = __float2bfloat16(h - __bfloat162float(hh));
                h0hi[outoff + (long long)b * H_ + j0 + u] = hh;
                h0lo[outoff + (long long)b * H_ + j0 + u] = hl;
            }
        } else if (!isL0 && s >= 1) {
            // ================= layer-1 step t = s-1 =================
            const int t = s - 1;
            float* gs = (float*)(sm8 + GS1_OFF);
            float* cs = (float*)(sm8 + CS1_OFF);
            float* bs = (float*)(sm8 + BS1_OFF);
            const uint32_t hsb = smb + HS1_OFF;
            const int nch = (t == 0) ? 4 : 8;

#pragma unroll
            for (int ni = 0; ni < 2; ni++)
#pragma unroll
                for (int e = 0; e < 4; e++) {
                    accA[ni][e] = 0.f; accB1[ni][e] = 0.f; accB2[ni][e] = 0.f;
                }

            const long long in0 = (long long)(t & 1) * B_ * H_;         // h0[t]
            const long long in1 = (long long)((t & 1) ^ 1) * B_ * H_;   // h1[t-1]

            auto issue = [&](int kc) {
                const __nv_bfloat16* shi = (kc < 4) ? h0hi + in0 + kc * 128
                                                    : h1hi + in1 + (kc - 4) * 128;
                const __nv_bfloat16* slo = (kc < 4) ? h0lo + in0 + kc * 128
                                                    : h1lo + in1 + (kc - 4) * 128;
#pragma unroll
                for (int i = 0; i < 8; i++) {
                    int idx = tx + i * 256;
                    int mat = idx >> 10;
                    int r   = (idx >> 4) & 63;
                    int seg = idx & 15;
                    const __nv_bfloat16* src = (mat ? slo : shi) + (long long)r * H_ + seg * 8;
                    uint32_t dst = hsb + (uint32_t)(kc & 1) * HC_BYTES
                                 + (uint32_t)mat * HC_MATB
                                 + (uint32_t)(r * 136 + seg * 8) * 2;
                    CP_ASYNC16(dst, src);
                }
                CP_COMMIT();
            };
            auto consume = [&](int kc) {
                const uint32_t hb = hsb + (uint32_t)(kc & 1) * HC_BYTES;
#pragma unroll
                for (int kk2 = 0; kk2 < 8; kk2++) {
                    uint32_t aH[4], aL[4];
                    int arow = mw * 16 + (lane & 7) + ((lane >> 3) & 1) * 8;
                    int acol = kk2 * 16 + (lane >> 4) * 8;
                    uint32_t ad = hb + (uint32_t)(arow * 136 + acol) * 2;
                    LDSM_X4(aH, ad);
                    LDSM_X4(aL, ad + HC_MATB);
                    int kg = kc * 8 + kk2;
#pragma unroll
                    for (int ni = 0; ni < 2; ni++) {
                        uint32_t bH[2], bL[2];
                        int brow = nw * 16 + ni * 8 + (l16 & 7);
                        int bcol = kg * 16 + (l16 >> 3) * 8;
                        uint32_t bd = smb + (uint32_t)(brow * WS1_STR + bcol) * 2;
                        LDSM_X2(bH, bd);
                        LDSM_X2(bL, bd + WS1_MATB);
                        mma16816(accA[ni],  aH, bH);
                        mma16816(accB1[ni], aH, bL);
                        mma16816(accB2[ni], aL, bH);
                    }
                }
            };

            issue(0);
            for (int kc = 0; kc < nch; kc++) {
                if (kc + 1 < nch) { issue(kc + 1); CP_WAIT(1); }
                else              { CP_WAIT(0); }
                __syncthreads();
                consume(kc);
                __syncthreads();   // WAR: buffer reuse by issue(kc+2)
            }

#pragma unroll
            for (int ni = 0; ni < 2; ni++) {
                int r = mw * 16 + (lane >> 2);
                int cb = nw * 16 + ni * 8 + (lane & 3) * 2;
                gs[r * 33 + cb]           = accA[ni][0] + accB1[ni][0] + accB2[ni][0];
                gs[r * 33 + cb + 1]       = accA[ni][1] + accB1[ni][1] + accB2[ni][1];
                gs[(r + 8) * 33 + cb]     = accA[ni][2] + accB1[ni][2] + accB2[ni][2];
                gs[(r + 8) * 33 + cb + 1] = accA[ni][3] + accB1[ni][3] + accB2[ni][3];
            }
            __syncthreads();

            const long long outoff = (long long)(t & 1) * B_ * H_;
#pragma unroll
            for (int i = 0; i < 2; i++) {
                int e = tx + i * 256;
                int b = e >> 3, u = e & 7;
                float gi = bs[0 * 8 + u] + gs[b * 33 + 0 * 8 + u];
                float gf = bs[1 * 8 + u] + gs[b * 33 + 1 * 8 + u];
                float gc = bs[2 * 8 + u] + gs[b * 33 + 2 * 8 + u];
                float go = bs[3 * 8 + u] + gs[b * 33 + 3 * 8 + u];
                float i_ = 1.f / (1.f + expf(-gi));
                float f_ = 1.f / (1.f + expf(-gf));
                float g_ = tanhf(gc);
                float o_ = 1.f / (1.f + expf(-go));
                float cold = (t == 0) ? 0.f : cs[e];
                float cn = f_ * cold + i_ * g_;
                cs[e] = cn;
                float h = o_ * tanhf(cn);
                __nv_bfloat16 hh = __float2bfloat16(h);
                __nv_bfloat16 hl = __float2bfloat16(h - __bfloat162float(hh));
                h1hi[outoff + (long long)b * H_ + j0 + u] = hh;
                h1lo[outoff + (long long)b * H_ + j0 + u] = hl;
            }
        }

        // ---- grid barrier between stages ----
        if (s < T_) {
            __syncthreads();
            if (tx == 0) {
                unsigned target = (unsigned)(s + 1) * (unsigned)gridDim.x;
                asm volatile("red.release.gpu.global.add.u32 [%0], %1;"
                             :: "l"(bar), "r"(1u) : "memory");
                unsigned v;
                do {
                    asm volatile("ld.acquire.gpu.global.u32 %0, [%1];"
                                 : "=r"(v) : "l"(bar) : "memory");
                } while (v < target);
            }
            __syncthreads();
        }
    }
}

// ---------------------------------------------------------------------------
// Final FC: h reconstructed from bf16 hi/lo pair
// ---------------------------------------------------------------------------
__global__ __launch_bounds__(128) void fc_kernel(
    const __nv_bfloat16* __restrict__ hhi, const __nv_bfloat16* __restrict__ hlo,
    const float* __restrict__ Wfc, const float* __restrict__ bfc,
    float* __restrict__ out)
{
    __shared__ float hrow[H_];
    int b = blockIdx.x;
    for (int k = threadIdx.x; k < H_; k += 128)
        hrow[k] = __bfloat162float(hhi[b * H_ + k]) + __bfloat162float(hlo[b * H_ + k]);
    __syncthreads();

    int o = threadIdx.x;
    float s = bfc[o];
    const float4* w4 = reinterpret_cast<const float4*>(Wfc + (size_t)o * H_);
    const float4* h4 = reinterpret_cast<const float4*>(hrow);
#pragma unroll 4
    for (int k = 0; k < H_ / 4; k++) {
        float4 w = w4[k];
        float4 hh = h4[k];
        s += w.x * hh.x + w.y * hh.y + w.z * hh.z + w.w * hh.w;
    }
    out[b * OUT_ + o] = s;
}

// ---------------------------------------------------------------------------
extern "C" void kernel_launch(void* const* d_in, const int* in_sizes, int n_in,
                              void* d_out, int out_size)
{
    const float* x     = (const float*)d_in[0];
    const float* W_ih0 = (const float*)d_in[1];
    const float* W_hh0 = (const float*)d_in[2];
    const float* b_ih0 = (const float*)d_in[3];
    const float* b_hh0 = (const float*)d_in[4];
    const float* W_ih1 = (const float*)d_in[5];
    const float* W_hh1 = (const float*)d_in[6];
    const float* b_ih1 = (const float*)d_in[7];
    const float* b_hh1 = (const float*)d_in[8];
    const float* W_fc  = (const float*)d_in[9];
    const float* b_fc  = (const float*)d_in[10];
    float* out = (float*)d_out;

    float* xp;
    unsigned* bar;
    __nv_bfloat16 *xhi, *xlo, *whi, *wlo, *h0hi, *h0lo, *h1hi, *h1lo;
    cudaGetSymbolAddress((void**)&xp,   g_xp);
    cudaGetSymbolAddress((void**)&bar,  g_bar);
    cudaGetSymbolAddress((void**)&xhi,  g_Xhi);
    cudaGetSymbolAddress((void**)&xlo,  g_Xlo);
    cudaGetSymbolAddress((void**)&whi,  g_Whi);
    cudaGetSymbolAddress((void**)&wlo,  g_Wlo);
    cudaGetSymbolAddress((void**)&h0hi, g_h0hi);
    cudaGetSymbolAddress((void**)&h0lo, g_h0lo);
    cudaGetSymbolAddress((void**)&h1hi, g_h1hi);
    cudaGetSymbolAddress((void**)&h1lo, g_h1lo);

    cudaFuncSetAttribute(gemm_mma_kernel,
                         cudaFuncAttributeMaxDynamicSharedMemorySize, GEMM_SMEM_BYTES);
    cudaFuncSetAttribute(lstm_fused_kernel,
                         cudaFuncAttributeMaxDynamicSharedMemorySize, FUSED_SMEM);

    dim3 mma_grid(G4_ / 128, M_ / 128);   // (16, 256)

    // layer-0 xp GEMM (K=128)
    {
        int nA = M_ * IN_;
        int nW = G4_ * IN_;
        split_bf16_kernel<<<(nA + 255) / 256, 256>>>(x, xhi, xlo, nA);
        split_bf16_kernel<<<(nW + 255) / 256, 256>>>(W_ih0, whi, wlo, nW);
        gemm_mma_kernel<<<mma_grid, 256, GEMM_SMEM_BYTES>>>(xhi, xlo, whi, wlo,
                                                            b_ih0, b_hh0, xp, IN_);
    }
    bar_init_kernel<<<1, 1>>>();

    // fused two-layer recurrence
    lstm_fused_kernel<<<FBLK, RTHR, FUSED_SMEM>>>(
        xp, W_hh0, W_ih1, W_hh1, b_ih1, b_hh1,
        h0hi, h0lo, h1hi, h1lo, bar);

    // final FC on h1[t=511] (parity 1)
    fc_kernel<<<B_, 128>>>(h1hi + (size_t)B_ * H_, h1lo + (size_t)B_ * H_,
                           W_fc, b_fc, out);
}

// round 8
// speedup vs baseline: 2.5560x; 1.0473x over previous
#include <cuda_runtime.h>
#include <cuda_bf16.h>
#include <math.h>
#include <stdint.h>

#define B_   64
#define T_   512
#define IN_  128
#define H_   512
#define G4_  2048   // 4*H
#define OUT_ 128
#define M_   (B_ * T_)   // 32768

#define FBLK 128    // fused grid: 64 layer-0 + 64 layer-1 blocks
#define RTHR 256

// ---------------- scratch (static device memory; no allocs) ----------------
__device__ float g_xp[(size_t)M_ * G4_];            // layer-0 gate preactivations
__device__ unsigned int g_bar;                      // grid barrier counter

__device__ __nv_bfloat16 g_Xhi[(size_t)M_ * IN_];   // x split
__device__ __nv_bfloat16 g_Xlo[(size_t)M_ * IN_];
__device__ __nv_bfloat16 g_Whi[(size_t)G4_ * IN_];  // W_ih0 split
__device__ __nv_bfloat16 g_Wlo[(size_t)G4_ * IN_];
__device__ __nv_bfloat16 g_h0hi[2 * B_ * H_];       // layer-0 h ping-pong
__device__ __nv_bfloat16 g_h0lo[2 * B_ * H_];
__device__ __nv_bfloat16 g_h1hi[2 * B_ * H_];       // layer-1 h ping-pong
__device__ __nv_bfloat16 g_h1lo[2 * B_ * H_];

__global__ void bar_init_kernel() { g_bar = 0u; }

// ======================= helpers ==============================
__device__ __forceinline__ uint32_t smem_u32(const void* p) {
    uint32_t a;
    asm("{ .reg .u64 t; cvta.to.shared.u64 t, %1; cvt.u32.u64 %0, t; }"
        : "=r"(a) : "l"(p));
    return a;
}

#define LDSM_X4(r, addr) \
    asm volatile("ldmatrix.sync.aligned.m8n8.x4.shared.b16 {%0,%1,%2,%3}, [%4];" \
        : "=r"((r)[0]), "=r"((r)[1]), "=r"((r)[2]), "=r"((r)[3]) : "r"(addr))
#define LDSM_X2(r, addr) \
    asm volatile("ldmatrix.sync.aligned.m8n8.x2.shared.b16 {%0,%1}, [%2];" \
        : "=r"((r)[0]), "=r"((r)[1]) : "r"(addr))

__device__ __forceinline__ void mma16816(float* d, const uint32_t* a, const uint32_t* b) {
    asm volatile("mma.sync.aligned.m16n8k16.row.col.f32.bf16.bf16.f32 "
        "{%0,%1,%2,%3}, {%4,%5,%6,%7}, {%8,%9}, {%0,%1,%2,%3};"
        : "+f"(d[0]), "+f"(d[1]), "+f"(d[2]), "+f"(d[3])
        : "r"(a[0]), "r"(a[1]), "r"(a[2]), "r"(a[3]), "r"(b[0]), "r"(b[1]));
}

#define CP_ASYNC16(dst, src) \
    asm volatile("cp.async.cg.shared.global [%0], [%1], 16;" :: "r"(dst), "l"(src))
#define CP_COMMIT() asm volatile("cp.async.commit_group;" ::: "memory")
#define CP_WAIT(n)  asm volatile("cp.async.wait_group %0;" :: "n"(n) : "memory")

// ---------------------------------------------------------------------------
// fp32 -> (hi, lo) bf16 split
// ---------------------------------------------------------------------------
__global__ __launch_bounds__(256) void split_bf16_kernel(
    const float* __restrict__ in, __nv_bfloat16* __restrict__ hi,
    __nv_bfloat16* __restrict__ lo, int n)
{
    int i = blockIdx.x * 256 + threadIdx.x;
    if (i < n) {
        float v = in[i];
        __nv_bfloat16 h = __float2bfloat16(v);
        hi[i] = h;
        lo[i] = __float2bfloat16(v - __bfloat162float(h));
    }
}

// ---------------------------------------------------------------------------
// bf16x3 GEMM via mma.sync (layer-0 xp only; unchanged, passing since R3)
// ---------------------------------------------------------------------------
#define GSTRIDE 40
#define SMAT    (128 * GSTRIDE)
#define SSTAGE  (4 * SMAT)
#define GEMM_SMEM_BYTES (2 * SSTAGE * 2 + 128 * 4)

__global__ __launch_bounds__(256) void gemm_mma_kernel(
    const __nv_bfloat16* __restrict__ Ahi, const __nv_bfloat16* __restrict__ Alo,
    const __nv_bfloat16* __restrict__ Whi, const __nv_bfloat16* __restrict__ Wlo,
    const float* __restrict__ b1, const float* __restrict__ b2,
    float* __restrict__ C, int K)
{
    extern __shared__ __nv_bfloat16 sm[];
    float* biass = (float*)(sm + 2 * SSTAGE);

    const int tid  = threadIdx.x;
    const int wid  = tid >> 5;
    const int lane = tid & 31;
    const int wm   = wid >> 2;
    const int wn   = wid & 3;
    const int m0   = blockIdx.y * 128;
    const int n0   = blockIdx.x * 128;

    if (tid < 128) biass[tid] = b1[n0 + tid] + b2[n0 + tid];

    const int K8 = K >> 3;
    const uint4* gA[2] = { (const uint4*)Ahi, (const uint4*)Alo };
    const uint4* gW[2] = { (const uint4*)Whi, (const uint4*)Wlo };
    const uint32_t smb = smem_u32(sm);

    auto prefetch = [&](int kt, int st) {
        const int kk8 = kt * 4;
        const uint32_t sbase = smb + (uint32_t)st * (SSTAGE * 2);
#pragma unroll
        for (int hl = 0; hl < 2; hl++) {
#pragma unroll
            for (int i = 0; i < 2; i++) {
                int idx = tid + i * 256;
                int r = idx >> 2, j = idx & 3;
                uint32_t dst = sbase + (uint32_t)(hl * SMAT + r * GSTRIDE) * 2 + j * 16;
                CP_ASYNC16(dst, gA[hl] + (size_t)(m0 + r) * K8 + kk8 + j);
            }
#pragma unroll
            for (int i = 0; i < 2; i++) {
                int idx = tid + i * 256;
                int r = idx >> 2, j = idx & 3;
                uint32_t dst = sbase + (uint32_t)((2 + hl) * SMAT + r * GSTRIDE) * 2 + j * 16;
                CP_ASYNC16(dst, gW[hl] + (size_t)(n0 + r) * K8 + kk8 + j);
            }
        }
        CP_COMMIT();
    };

    float acc[4][4][4];
#pragma unroll
    for (int mi = 0; mi < 4; mi++)
#pragma unroll
        for (int ni = 0; ni < 4; ni++)
#pragma unroll
            for (int e = 0; e < 4; e++) acc[mi][ni][e] = 0.f;

    const int KT = K / 32;
    prefetch(0, 0);

    for (int kt = 0; kt < KT; kt++) {
        if (kt + 1 < KT) { prefetch(kt + 1, (kt + 1) & 1); CP_WAIT(1); }
        else             { CP_WAIT(0); }
        __syncthreads();

        const uint32_t sbase = smb + (uint32_t)(kt & 1) * (SSTAGE * 2);
#pragma unroll
        for (int ks = 0; ks < 2; ks++) {
            uint32_t aH[4][4], aL[4][4], bH[4][2], bL[4][2];

            const int arow = wm * 64 + (lane & 7) + ((lane >> 3) & 1) * 8;
            const int acol = ks * 16 + (lane >> 4) * 8;
#pragma unroll
            for (int mi = 0; mi < 4; mi++) {
                uint32_t ad = sbase + (uint32_t)((arow + mi * 16) * GSTRIDE + acol) * 2;
                LDSM_X4(aH[mi], ad);
                LDSM_X4(aL[mi], ad + SMAT * 2);
            }
            const int l16  = lane & 15;
            const int brow = wn * 32 + (l16 & 7);
            const int bcol = ks * 16 + (l16 >> 3) * 8;
#pragma unroll
            for (int ni = 0; ni < 4; ni++) {
                uint32_t bd = sbase + (uint32_t)(2 * SMAT + (brow + ni * 8) * GSTRIDE + bcol) * 2;
                LDSM_X2(bH[ni], bd);
                LDSM_X2(bL[ni], bd + SMAT * 2);
            }
#pragma unroll
            for (int mi = 0; mi < 4; mi++)
#pragma unroll
                for (int ni = 0; ni < 4; ni++) {
                    mma16816(acc[mi][ni], aH[mi], bH[ni]);
                    mma16816(acc[mi][ni], aH[mi], bL[ni]);
                    mma16816(acc[mi][ni], aL[mi], bH[ni]);
                }
        }
        __syncthreads();
    }

#pragma unroll
    for (int mi = 0; mi < 4; mi++) {
        const int r0 = m0 + wm * 64 + mi * 16 + (lane >> 2);
#pragma unroll
        for (int ni = 0; ni < 4; ni++) {
            const int c = wn * 32 + ni * 8 + (lane & 3) * 2;
            float2 v0, v1;
            v0.x = acc[mi][ni][0] + biass[c];
            v0.y = acc[mi][ni][1] + biass[c + 1];
            v1.x = acc[mi][ni][2] + biass[c];
            v1.y = acc[mi][ni][3] + biass[c + 1];
            *(float2*)&C[(size_t)r0 * G4_ + n0 + c]       = v0;
            *(float2*)&C[(size_t)(r0 + 8) * G4_ + n0 + c] = v1;
        }
    }
}

// ---------------------------------------------------------------------------
// FUSED two-layer persistent LSTM. 128 blocks x 256 threads.
// Blocks 0..63  : layer 0 (K=512 vs h0[t-1]), xp from g_xp, 4x128-col chunks
//                 fully resident per step.
// Blocks 64..127: layer 1 (K=1024 vs [h0[t] ; h1[t-1]]), [W_ih1;W_hh1]
//                 resident; 16x64-col chunks through a 4-deep cp.async ring
//                 (CUTLASS-style: one syncthreads per chunk, empty commit
//                 groups at the tail keep the wait-count invariant).
// ---------------------------------------------------------------------------
// layer-0 SMEM layout
#define WS0_MATB  33280u            // 32*520*2
#define HS0_OFF   66560u
#define HC_MATB   17408u            // 64*136*2
#define HC_BYTES  34816u            // hi+lo per 128-col chunk
#define XS0_OFF   205824u           // HS0_OFF + 4*HC_BYTES
#define GS0_OFF   214016u
#define CS0_OFF   222464u
// layer-1 SMEM layout
#define WS1_STR   1048              // elems per weight row (2096 B)
#define WS1_MATB  67072u            // 32*1048*2
#define HS1_OFF   134144u           // 4 ring buffers of 64-col chunks
#define HC1_MATB  9216u             // 64*72*2
#define HC1_BYTES 18432u            // hi+lo per 64-col chunk
#define GS1_OFF   207872u           // HS1_OFF + 4*HC1_BYTES
#define CS1_OFF   216320u
#define BS1_OFF   218368u
#define FUSED_SMEM 224512

__global__ __launch_bounds__(RTHR, 1) void lstm_fused_kernel(
    const float* __restrict__ xp0, const float* __restrict__ Whh0,
    const float* __restrict__ Wih1, const float* __restrict__ Whh1,
    const float* __restrict__ b_ih1, const float* __restrict__ b_hh1,
    __nv_bfloat16* __restrict__ h0hi, __nv_bfloat16* __restrict__ h0lo,
    __nv_bfloat16* __restrict__ h1hi, __nv_bfloat16* __restrict__ h1lo,
    unsigned* __restrict__ bar)
{
    extern __shared__ char sm8[];
    const int tx   = threadIdx.x;
    const int wid  = tx >> 5;
    const int lane = tx & 31;
    const int l16  = lane & 15;
    const int mw   = wid >> 1;           // 0..3
    const int nw   = wid & 1;            // 0..1
    const bool isL0 = blockIdx.x < 64;
    const int j0   = (blockIdx.x & 63) * 8;

    const uint32_t smb = smem_u32(sm8);
    __nv_bfloat16* ws = (__nv_bfloat16*)sm8;

    if (isL0) {
        // ---- layer-0 setup: split W_hh0 slice into SMEM (stride 520) ----
#pragma unroll 4
        for (int i = 0; i < 64; i++) {
            int idx = tx + i * 256;
            int cc = idx >> 9, k = idx & 511;
            int gg = cc >> 3, u = cc & 7;
            float w = Whh0[(size_t)(gg * H_ + j0 + u) * H_ + k];
            __nv_bfloat16 wh = __float2bfloat16(w);
            ws[cc * 520 + k] = wh;
            ws[16640 + cc * 520 + k] = __float2bfloat16(w - __bfloat162float(wh));
        }
    } else {
        // ---- layer-1 setup: split [W_ih1 ; W_hh1] slice (stride 1048) ----
#pragma unroll 4
        for (int i = 0; i < 128; i++) {
            int idx = tx + i * 256;          // 0..32767
            int cc = idx >> 10, k = idx & 1023;
            int gg = cc >> 3, u = cc & 7;
            size_t row = (size_t)(gg * H_ + j0 + u) * H_;
            float w = (k < 512) ? Wih1[row + k] : Whh1[row + k - 512];
            __nv_bfloat16 wh = __float2bfloat16(w);
            ws[cc * WS1_STR + k] = wh;
            ws[33536 + cc * WS1_STR + k] = __float2bfloat16(w - __bfloat162float(wh));
        }
        if (tx < 32) {
            int gg = tx >> 3, u = tx & 7;
            ((float*)(sm8 + BS1_OFF))[tx] =
                b_ih1[gg * H_ + j0 + u] + b_hh1[gg * H_ + j0 + u];
        }
    }
    __syncthreads();

    float accA[2][4], accB1[2][4], accB2[2][4];

    for (int s = 0; s <= T_; s++) {
        if (isL0 && s < T_) {
            // ================= layer-0 step s =================
            const int t = s;
            float* xs = (float*)(sm8 + XS0_OFF);
            float* gs = (float*)(sm8 + GS0_OFF);
            float* cs = (float*)(sm8 + CS0_OFF);
            const uint32_t hsb = smb + HS0_OFF;

            // group 0: xp tile
#pragma unroll
            for (int i = 0; i < 2; i++) {
                int idx = tx + i * 256;
                int b = idx >> 3, gg = (idx >> 1) & 3, seg = idx & 1;
                uint32_t dst = smb + XS0_OFF + (uint32_t)(b * 32 + gg * 8 + seg * 4) * 4;
                CP_ASYNC16(dst, xp0 + ((size_t)b * T_ + t) * G4_ + gg * H_ + j0 + seg * 4);
            }
            CP_COMMIT();

#pragma unroll
            for (int ni = 0; ni < 2; ni++)
#pragma unroll
                for (int e = 0; e < 4; e++) {
                    accA[ni][e] = 0.f; accB1[ni][e] = 0.f; accB2[ni][e] = 0.f;
                }

            if (t > 0) {
                const long long inoff = (long long)((t & 1) ^ 1) * B_ * H_;
#pragma unroll
                for (int c = 0; c < 4; c++) {
#pragma unroll
                    for (int i = 0; i < 8; i++) {
                        int idx = tx + i * 256;
                        int mat = idx >> 10;
                        int r   = (idx >> 4) & 63;
                        int seg = idx & 15;
                        const __nv_bfloat16* src =
                            (mat ? h0lo : h0hi) + inoff + (long long)r * H_ + c * 128 + seg * 8;
                        uint32_t dst = hsb + (uint32_t)c * HC_BYTES
                                     + (uint32_t)mat * HC_MATB
                                     + (uint32_t)(r * 136 + seg * 8) * 2;
                        CP_ASYNC16(dst, src);
                    }
                    CP_COMMIT();
                }

                auto consume = [&](int c) {
                    const uint32_t hb = hsb + (uint32_t)c * HC_BYTES;
#pragma unroll
                    for (int kk2 = 0; kk2 < 8; kk2++) {
                        uint32_t aH[4], aL[4];
                        int arow = mw * 16 + (lane & 7) + ((lane >> 3) & 1) * 8;
                        int acol = kk2 * 16 + (lane >> 4) * 8;
                        uint32_t ad = hb + (uint32_t)(arow * 136 + acol) * 2;
                        LDSM_X4(aH, ad);
                        LDSM_X4(aL, ad + HC_MATB);
                        int kg = c * 8 + kk2;
#pragma unroll
                        for (int ni = 0; ni < 2; ni++) {
                            uint32_t bH[2], bL[2];
                            int brow = nw * 16 + ni * 8 + (l16 & 7);
                            int bcol = kg * 16 + (l16 >> 3) * 8;
                            uint32_t bd = smb + (uint32_t)(brow * 520 + bcol) * 2;
                            LDSM_X2(bH, bd);
                            LDSM_X2(bL, bd + WS0_MATB);
                            mma16816(accA[ni],  aH, bH);
                            mma16816(accB1[ni], aH, bL);
                            mma16816(accB2[ni], aL, bH);
                        }
                    }
                };
                CP_WAIT(3); __syncthreads(); consume(0);
                CP_WAIT(2); __syncthreads(); consume(1);
                CP_WAIT(1); __syncthreads(); consume(2);
                CP_WAIT(0); __syncthreads(); consume(3);

#pragma unroll
                for (int ni = 0; ni < 2; ni++) {
                    int r = mw * 16 + (lane >> 2);
                    int cb = nw * 16 + ni * 8 + (lane & 3) * 2;
                    gs[r * 33 + cb]           = accA[ni][0] + accB1[ni][0] + accB2[ni][0];
                    gs[r * 33 + cb + 1]       = accA[ni][1] + accB1[ni][1] + accB2[ni][1];
                    gs[(r + 8) * 33 + cb]     = accA[ni][2] + accB1[ni][2] + accB2[ni][2];
                    gs[(r + 8) * 33 + cb + 1] = accA[ni][3] + accB1[ni][3] + accB2[ni][3];
                }
            } else {
                CP_WAIT(0);
            }
            __syncthreads();

            const long long outoff = (long long)(t & 1) * B_ * H_;
#pragma unroll
            for (int i = 0; i < 2; i++) {
                int e = tx + i * 256;
                int b = e >> 3, u = e & 7;
                float gi = xs[b * 32 + 0 * 8 + u];
                float gf = xs[b * 32 + 1 * 8 + u];
                float gc = xs[b * 32 + 2 * 8 + u];
                float go = xs[b * 32 + 3 * 8 + u];
                if (t > 0) {
                    gi += gs[b * 33 + 0 * 8 + u];
                    gf += gs[b * 33 + 1 * 8 + u];
                    gc += gs[b * 33 + 2 * 8 + u];
                    go += gs[b * 33 + 3 * 8 + u];
                }
                float i_ = 1.f / (1.f + expf(-gi));
                float f_ = 1.f / (1.f + expf(-gf));
                float g_ = tanhf(gc);
                float o_ = 1.f / (1.f + expf(-go));
                float cold = (t == 0) ? 0.f : cs[e];
                float cn = f_ * cold + i_ * g_;
                cs[e] = cn;
                float h = o_ * tanhf(cn);
                __nv_bfloat16 hh = __float2bfloat16(h);
                __nv_bfloat16 hl = __float2bfloat16(h - __bfloat162float(hh));
                h0hi[outoff + (long long)b * H_ + j0 + u] = hh;
                h0lo[outoff + (long long)b * H_ + j0 + u] = hl;
            }
        } else if (!isL0 && s >= 1) {
            // ================= layer-1 step t = s-1 =================
            const int t = s - 1;
            float* gs = (float*)(sm8 + GS1_OFF);
            float* cs = (float*)(sm8 + CS1_OFF);
            float* bs = (float*)(sm8 + BS1_OFF);
            const uint32_t hsb = smb + HS1_OFF;
            const int nch = (t == 0) ? 8 : 16;   // 64-col chunks of concat K

#pragma unroll
            for (int ni = 0; ni < 2; ni++)
#pragma unroll
                for (int e = 0; e < 4; e++) {
                    accA[ni][e] = 0.f; accB1[ni][e] = 0.f; accB2[ni][e] = 0.f;
                }

            const long long in0 = (long long)(t & 1) * B_ * H_;         // h0[t]
            const long long in1 = (long long)((t & 1) ^ 1) * B_ * H_;   // h1[t-1]

            auto issue = [&](int kc) {
                const __nv_bfloat16* shi;
                const __nv_bfloat16* slo;
                int coff;
                if (kc < 8) { shi = h0hi + in0; slo = h0lo + in0; coff = kc * 64; }
                else        { shi = h1hi + in1; slo = h1lo + in1; coff = (kc - 8) * 64; }
#pragma unroll
                for (int i = 0; i < 4; i++) {
                    int idx = tx + i * 256;          // 0..1023
                    int mat = idx >> 9;
                    int r   = (idx >> 3) & 63;
                    int seg = idx & 7;
                    const __nv_bfloat16* src = (mat ? slo : shi) + (long long)r * H_ + coff + seg * 8;
                    uint32_t dst = hsb + (uint32_t)(kc & 3) * HC1_BYTES
                                 + (uint32_t)mat * HC1_MATB
                                 + (uint32_t)(r * 72 + seg * 8) * 2;
                    CP_ASYNC16(dst, src);
                }
                CP_COMMIT();
            };
            auto consume = [&](int kc) {
                const uint32_t hb = hsb + (uint32_t)(kc & 3) * HC1_BYTES;
#pragma unroll
                for (int kk2 = 0; kk2 < 4; kk2++) {
                    uint32_t aH[4], aL[4];
                    int arow = mw * 16 + (lane & 7) + ((lane >> 3) & 1) * 8;
                    int acol = kk2 * 16 + (lane >> 4) * 8;
                    uint32_t ad = hb + (uint32_t)(arow * 72 + acol) * 2;
                    LDSM_X4(aH, ad);
                    LDSM_X4(aL, ad + HC1_MATB);
                    int kg = kc * 4 + kk2;           // global k-tile 0..63
#pragma unroll
                    for (int ni = 0; ni < 2; ni++) {
                        uint32_t bH[2], bL[2];
                        int brow = nw * 16 + ni * 8 + (l16 & 7);
                        int bcol = kg * 16 + (l16 >> 3) * 8;
                        uint32_t bd = smb + (uint32_t)(brow * WS1_STR + bcol) * 2;
                        LDSM_X2(bH, bd);
                        LDSM_X2(bL, bd + WS1_MATB);
                        mma16816(accA[ni],  aH, bH);
                        mma16816(accB1[ni], aH, bL);
                        mma16816(accB2[ni], aL, bH);
                    }
                }
            };

            // 4-deep ring, issue depth 3, one syncthreads per chunk
            issue(0); issue(1); issue(2);
            CP_WAIT(2); __syncthreads();
            for (int kc = 0; kc < nch; kc++) {
                consume(kc);
                if (kc + 3 < nch) issue(kc + 3);
                else              CP_COMMIT();       // empty group keeps count
                CP_WAIT(2); __syncthreads();
            }

#pragma unroll
            for (int ni = 0; ni < 2; ni++) {
                int r = mw * 16 + (lane >> 2);
                int cb = nw * 16 + ni * 8 + (lane & 3) * 2;
                gs[r * 33 + cb]           = accA[ni][0] + accB1[ni][0] + accB2[ni][0];
                gs[r * 33 + cb + 1]       = accA[ni][1] + accB1[ni][1] + accB2[ni][1];
                gs[(r + 8) * 33 + cb]     = accA[ni][2] + accB1[ni][2] + accB2[ni][2];
                gs[(r + 8) * 33 + cb + 1] = accA[ni][3] + accB1[ni][3] + accB2[ni][3];
            }
            __syncthreads();

            const long long outoff = (long long)(t & 1) * B_ * H_;
#pragma unroll
            for (int i = 0; i < 2; i++) {
                int e = tx + i * 256;
                int b = e >> 3, u = e & 7;
                float gi = bs[0 * 8 + u] + gs[b * 33 + 0 * 8 + u];
                float gf = bs[1 * 8 + u] + gs[b * 33 + 1 * 8 + u];
                float gc = bs[2 * 8 + u] + gs[b * 33 + 2 * 8 + u];
                float go = bs[3 * 8 + u] + gs[b * 33 + 3 * 8 + u];
                float i_ = 1.f / (1.f + expf(-gi));
                float f_ = 1.f / (1.f + expf(-gf));
                float g_ = tanhf(gc);
                float o_ = 1.f / (1.f + expf(-go));
                float cold = (t == 0) ? 0.f : cs[e];
                float cn = f_ * cold + i_ * g_;
                cs[e] = cn;
                float h = o_ * tanhf(cn);
                __nv_bfloat16 hh = __float2bfloat16(h);
                __nv_bfloat16 hl = __float2bfloat16(h - __bfloat162float(hh));
                h1hi[outoff + (long long)b * H_ + j0 + u] = hh;
                h1lo[outoff + (long long)b * H_ + j0 + u] = hl;
            }
        }

        // ---- grid barrier between stages ----
        if (s < T_) {
            __syncthreads();
            if (tx == 0) {
                unsigned target = (unsigned)(s + 1) * (unsigned)gridDim.x;
                asm volatile("red.release.gpu.global.add.u32 [%0], %1;"
                             :: "l"(bar), "r"(1u) : "memory");
                unsigned v;
                do {
                    asm volatile("ld.acquire.gpu.global.u32 %0, [%1];"
                                 : "=r"(v) : "l"(bar) : "memory");
                } while (v < target);
            }
            __syncthreads();
        }
    }
}

// ---------------------------------------------------------------------------
// Final FC: h reconstructed from bf16 hi/lo pair
// ---------------------------------------------------------------------------
__global__ __launch_bounds__(128) void fc_kernel(
    const __nv_bfloat16* __restrict__ hhi, const __nv_bfloat16* __restrict__ hlo,
    const float* __restrict__ Wfc, const float* __restrict__ bfc,
    float* __restrict__ out)
{
    __shared__ float hrow[H_];
    int b = blockIdx.x;
    for (int k = threadIdx.x; k < H_; k += 128)
        hrow[k] = __bfloat162float(hhi[b * H_ + k]) + __bfloat162float(hlo[b * H_ + k]);
    __syncthreads();

    int o = threadIdx.x;
    float s = bfc[o];
    const float4* w4 = reinterpret_cast<const float4*>(Wfc + (size_t)o * H_);
    const float4* h4 = reinterpret_cast<const float4*>(hrow);
#pragma unroll 4
    for (int k = 0; k < H_ / 4; k++) {
        float4 w = w4[k];
        float4 hh = h4[k];
        s += w.x * hh.x + w.y * hh.y + w.z * hh.z + w.w * hh.w;
    }
    out[b * OUT_ + o] = s;
}

// ---------------------------------------------------------------------------
extern "C" void kernel_launch(void* const* d_in, const int* in_sizes, int n_in,
                              void* d_out, int out_size)
{
    const float* x     = (const float*)d_in[0];
    const float* W_ih0 = (const float*)d_in[1];
    const float* W_hh0 = (const float*)d_in[2];
    const float* b_ih0 = (const float*)d_in[3];
    const float* b_hh0 = (const float*)d_in[4];
    const float* W_ih1 = (const float*)d_in[5];
    const float* W_hh1 = (const float*)d_in[6];
    const float* b_ih1 = (const float*)d_in[7];
    const float* b_hh1 = (const float*)d_in[8];
    const float* W_fc  = (const float*)d_in[9];
    const float* b_fc  = (const float*)d_in[10];
    float* out = (float*)d_out;

    float* xp;
    unsigned* bar;
    __nv_bfloat16 *xhi, *xlo, *whi, *wlo, *h0hi, *h0lo, *h1hi, *h1lo;
    cudaGetSymbolAddress((void**)&xp,   g_xp);
    cudaGetSymbolAddress((void**)&bar,  g_bar);
    cudaGetSymbolAddress((void**)&xhi,  g_Xhi);
    cudaGetSymbolAddress((void**)&xlo,  g_Xlo);
    cudaGetSymbolAddress((void**)&whi,  g_Whi);
    cudaGetSymbolAddress((void**)&wlo,  g_Wlo);
    cudaGetSymbolAddress((void**)&h0hi, g_h0hi);
    cudaGetSymbolAddress((void**)&h0lo, g_h0lo);
    cudaGetSymbolAddress((void**)&h1hi, g_h1hi);
    cudaGetSymbolAddress((void**)&h1lo, g_h1lo);

    cudaFuncSetAttribute(gemm_mma_kernel,
                         cudaFuncAttributeMaxDynamicSharedMemorySize, GEMM_SMEM_BYTES);
    cudaFuncSetAttribute(lstm_fused_kernel,
                         cudaFuncAttributeMaxDynamicSharedMemorySize, FUSED_SMEM);

    dim3 mma_grid(G4_ / 128, M_ / 128);   // (16, 256)

    // layer-0 xp GEMM (K=128)
    {
        int nA = M_ * IN_;
        int nW = G4_ * IN_;
        split_bf16_kernel<<<(nA + 255) / 256, 256>>>(x, xhi, xlo, nA);
        split_bf16_kernel<<<(nW + 255) / 256, 256>>>(W_ih0, whi, wlo, nW);
        gemm_mma_kernel<<<mma_grid, 256, GEMM_SMEM_BYTES>>>(xhi, xlo, whi, wlo,
                                                            b_ih0, b_hh0, xp, IN_);
    }
    bar_init_kernel<<<1, 1>>>();

    // fused two-layer recurrence
    lstm_fused_kernel<<<FBLK, RTHR, FUSED_SMEM>>>(
        xp, W_hh0, W_ih1, W_hh1, b_ih1, b_hh1,
        h0hi, h0lo, h1hi, h1lo, bar);

    // final FC on h1[t=511] (parity 1)
    fc_kernel<<<B_, 128>>>(h1hi + (size_t)B_ * H_, h1lo + (size_t)B_ * H_,
                           W_fc, b_fc, out);
}

// round 9
// speedup vs baseline: 3.4095x; 1.3339x over previous
#include <cuda_runtime.h>
#include <cuda_bf16.h>
#include <cuda_fp16.h>
#include <math.h>
#include <stdint.h>

#define B_   64
#define T_   512
#define IN_  128
#define H_   512
#define G4_  2048   // 4*H
#define OUT_ 128
#define M_   (B_ * T_)   // 32768

#define FBLK 128    // fused grid: 64 layer-0 + 64 layer-1 blocks
#define RTHR 256

// ---------------- scratch (static device memory; no allocs) ----------------
__device__ float g_xp[(size_t)M_ * G4_];            // layer-0 gate preactivations
__device__ unsigned int g_bar;                      // grid barrier counter

__device__ __nv_bfloat16 g_Xhi[(size_t)M_ * IN_];   // x split (front GEMM, bf16x3)
__device__ __nv_bfloat16 g_Xlo[(size_t)M_ * IN_];
__device__ __nv_bfloat16 g_Whi[(size_t)G4_ * IN_];  // W_ih0 split
__device__ __nv_bfloat16 g_Wlo[(size_t)G4_ * IN_];
__device__ __half g_h0[2 * B_ * H_];                // layer-0 h ping-pong (fp16)
__device__ __half g_h1[2 * B_ * H_];                // layer-1 h ping-pong (fp16)

__global__ void bar_init_kernel() { g_bar = 0u; }

// ======================= helpers ==============================
__device__ __forceinline__ uint32_t smem_u32(const void* p) {
    uint32_t a;
    asm("{ .reg .u64 t; cvta.to.shared.u64 t, %1; cvt.u32.u64 %0, t; }"
        : "=r"(a) : "l"(p));
    return a;
}

#define LDSM_X4(r, addr) \
    asm volatile("ldmatrix.sync.aligned.m8n8.x4.shared.b16 {%0,%1,%2,%3}, [%4];" \
        : "=r"((r)[0]), "=r"((r)[1]), "=r"((r)[2]), "=r"((r)[3]) : "r"(addr))
#define LDSM_X2(r, addr) \
    asm volatile("ldmatrix.sync.aligned.m8n8.x2.shared.b16 {%0,%1}, [%2];" \
        : "=r"((r)[0]), "=r"((r)[1]) : "r"(addr))

__device__ __forceinline__ void mma_bf16(float* d, const uint32_t* a, const uint32_t* b) {
    asm volatile("mma.sync.aligned.m16n8k16.row.col.f32.bf16.bf16.f32 "
        "{%0,%1,%2,%3}, {%4,%5,%6,%7}, {%8,%9}, {%0,%1,%2,%3};"
        : "+f"(d[0]), "+f"(d[1]), "+f"(d[2]), "+f"(d[3])
        : "r"(a[0]), "r"(a[1]), "r"(a[2]), "r"(a[3]), "r"(b[0]), "r"(b[1]));
}
__device__ __forceinline__ void mma_f16(float* d, const uint32_t* a, const uint32_t* b) {
    asm volatile("mma.sync.aligned.m16n8k16.row.col.f32.f16.f16.f32 "
        "{%0,%1,%2,%3}, {%4,%5,%6,%7}, {%8,%9}, {%0,%1,%2,%3};"
        : "+f"(d[0]), "+f"(d[1]), "+f"(d[2]), "+f"(d[3])
        : "r"(a[0]), "r"(a[1]), "r"(a[2]), "r"(a[3]), "r"(b[0]), "r"(b[1]));
}

#define CP_ASYNC16(dst, src) \
    asm volatile("cp.async.cg.shared.global [%0], [%1], 16;" :: "r"(dst), "l"(src))
#define CP_COMMIT() asm volatile("cp.async.commit_group;" ::: "memory")
#define CP_WAIT(n)  asm volatile("cp.async.wait_group %0;" :: "n"(n) : "memory")

// ---------------------------------------------------------------------------
// fp32 -> (hi, lo) bf16 split
// ---------------------------------------------------------------------------
__global__ __launch_bounds__(256) void split_bf16_kernel(
    const float* __restrict__ in, __nv_bfloat16* __restrict__ hi,
    __nv_bfloat16* __restrict__ lo, int n)
{
    int i = blockIdx.x * 256 + threadIdx.x;
    if (i < n) {
        float v = in[i];
        __nv_bfloat16 h = __float2bfloat16(v);
        hi[i] = h;
        lo[i] = __float2bfloat16(v - __bfloat162float(h));
    }
}

// ---------------------------------------------------------------------------
// bf16x3 GEMM via mma.sync (layer-0 xp only; unchanged, passing since R3)
// ---------------------------------------------------------------------------
#define GSTRIDE 40
#define SMAT    (128 * GSTRIDE)
#define SSTAGE  (4 * SMAT)
#define GEMM_SMEM_BYTES (2 * SSTAGE * 2 + 128 * 4)

__global__ __launch_bounds__(256) void gemm_mma_kernel(
    const __nv_bfloat16* __restrict__ Ahi, const __nv_bfloat16* __restrict__ Alo,
    const __nv_bfloat16* __restrict__ Whi, const __nv_bfloat16* __restrict__ Wlo,
    const float* __restrict__ b1, const float* __restrict__ b2,
    float* __restrict__ C, int K)
{
    extern __shared__ __nv_bfloat16 sm[];
    float* biass = (float*)(sm + 2 * SSTAGE);

    const int tid  = threadIdx.x;
    const int wid  = tid >> 5;
    const int lane = tid & 31;
    const int wm   = wid >> 2;
    const int wn   = wid & 3;
    const int m0   = blockIdx.y * 128;
    const int n0   = blockIdx.x * 128;

    if (tid < 128) biass[tid] = b1[n0 + tid] + b2[n0 + tid];

    const int K8 = K >> 3;
    const uint4* gA[2] = { (const uint4*)Ahi, (const uint4*)Alo };
    const uint4* gW[2] = { (const uint4*)Whi, (const uint4*)Wlo };
    const uint32_t smb = smem_u32(sm);

    auto prefetch = [&](int kt, int st) {
        const int kk8 = kt * 4;
        const uint32_t sbase = smb + (uint32_t)st * (SSTAGE * 2);
#pragma unroll
        for (int hl = 0; hl < 2; hl++) {
#pragma unroll
            for (int i = 0; i < 2; i++) {
                int idx = tid + i * 256;
                int r = idx >> 2, j = idx & 3;
                uint32_t dst = sbase + (uint32_t)(hl * SMAT + r * GSTRIDE) * 2 + j * 16;
                CP_ASYNC16(dst, gA[hl] + (size_t)(m0 + r) * K8 + kk8 + j);
            }
#pragma unroll
            for (int i = 0; i < 2; i++) {
                int idx = tid + i * 256;
                int r = idx >> 2, j = idx & 3;
                uint32_t dst = sbase + (uint32_t)((2 + hl) * SMAT + r * GSTRIDE) * 2 + j * 16;
                CP_ASYNC16(dst, gW[hl] + (size_t)(n0 + r) * K8 + kk8 + j);
            }
        }
        CP_COMMIT();
    };

    float acc[4][4][4];
#pragma unroll
    for (int mi = 0; mi < 4; mi++)
#pragma unroll
        for (int ni = 0; ni < 4; ni++)
#pragma unroll
            for (int e = 0; e < 4; e++) acc[mi][ni][e] = 0.f;

    const int KT = K / 32;
    prefetch(0, 0);

    for (int kt = 0; kt < KT; kt++) {
        if (kt + 1 < KT) { prefetch(kt + 1, (kt + 1) & 1); CP_WAIT(1); }
        else             { CP_WAIT(0); }
        __syncthreads();

        const uint32_t sbase = smb + (uint32_t)(kt & 1) * (SSTAGE * 2);
#pragma unroll
        for (int ks = 0; ks < 2; ks++) {
            uint32_t aH[4][4], aL[4][4], bH[4][2], bL[4][2];

            const int arow = wm * 64 + (lane & 7) + ((lane >> 3) & 1) * 8;
            const int acol = ks * 16 + (lane >> 4) * 8;
#pragma unroll
            for (int mi = 0; mi < 4; mi++) {
                uint32_t ad = sbase + (uint32_t)((arow + mi * 16) * GSTRIDE + acol) * 2;
                LDSM_X4(aH[mi], ad);
                LDSM_X4(aL[mi], ad + SMAT * 2);
            }
            const int l16  = lane & 15;
            const int brow = wn * 32 + (l16 & 7);
            const int bcol = ks * 16 + (l16 >> 3) * 8;
#pragma unroll
            for (int ni = 0; ni < 4; ni++) {
                uint32_t bd = sbase + (uint32_t)(2 * SMAT + (brow + ni * 8) * GSTRIDE + bcol) * 2;
                LDSM_X2(bH[ni], bd);
                LDSM_X2(bL[ni], bd + SMAT * 2);
            }
#pragma unroll
            for (int mi = 0; mi < 4; mi++)
#pragma unroll
                for (int ni = 0; ni < 4; ni++) {
                    mma_bf16(acc[mi][ni], aH[mi], bH[ni]);
                    mma_bf16(acc[mi][ni], aH[mi], bL[ni]);
                    mma_bf16(acc[mi][ni], aL[mi], bH[ni]);
                }
        }
        __syncthreads();
    }

#pragma unroll
    for (int mi = 0; mi < 4; mi++) {
        const int r0 = m0 + wm * 64 + mi * 16 + (lane >> 2);
#pragma unroll
        for (int ni = 0; ni < 4; ni++) {
            const int c = wn * 32 + ni * 8 + (lane & 3) * 2;
            float2 v0, v1;
            v0.x = acc[mi][ni][0] + biass[c];
            v0.y = acc[mi][ni][1] + biass[c + 1];
            v1.x = acc[mi][ni][2] + biass[c];
            v1.y = acc[mi][ni][3] + biass[c + 1];
            *(float2*)&C[(size_t)r0 * G4_ + n0 + c]       = v0;
            *(float2*)&C[(size_t)(r0 + 8) * G4_ + n0 + c] = v1;
        }
    }
}

// ---------------------------------------------------------------------------
// FUSED two-layer persistent LSTM, fp16x2 (h single fp16, W fp16 hi+lo).
// Blocks 0..63  : layer 0 (K=512 vs h0[t-1]); 4x128-col chunks resident.
// Blocks 64..127: layer 1 (K=1024 vs [h0[t] ; h1[t-1]]); 16x64-col chunks
//                 through a 4-deep cp.async ring.
// Per k16 tile: 1 A-LDSM_X4 + 2 B-LDSM_X4 (hi,lo; each covers both N8) and
// 4 HMMA (2 ni x {wH, wL}).
// ---------------------------------------------------------------------------
// layer-0 SMEM layout
#define WS0_STR   520
#define WS0_MATB  33280u            // 32*520*2
#define HS0_OFF   66560u            // 4 chunks of 64x136 fp16
#define HC0_BYTES 17408u            // 64*136*2
#define XS0_OFF   136192u           // HS0_OFF + 4*HC0_BYTES
#define GS0_OFF   144384u
#define CS0_OFF   152832u           // + 2048 -> 154880
// layer-1 SMEM layout
#define WS1_STR   1048
#define WS1_MATB  67072u            // 32*1048*2
#define HS1_OFF   134144u           // 4 ring buffers of 64x72 fp16
#define HC1_BYTES 9216u             // 64*72*2
#define GS1_OFF   171008u           // HS1_OFF + 4*HC1_BYTES
#define CS1_OFF   179456u
#define BS1_OFF   181504u           // + 128 -> 181632
#define FUSED_SMEM 182272

__global__ __launch_bounds__(RTHR, 1) void lstm_fused_kernel(
    const float* __restrict__ xp0, const float* __restrict__ Whh0,
    const float* __restrict__ Wih1, const float* __restrict__ Whh1,
    const float* __restrict__ b_ih1, const float* __restrict__ b_hh1,
    __half* __restrict__ h0, __half* __restrict__ h1,
    unsigned* __restrict__ bar)
{
    extern __shared__ char sm8[];
    const int tx   = threadIdx.x;
    const int wid  = tx >> 5;
    const int lane = tx & 31;
    const int mw   = wid >> 1;           // 0..3  (M16 of 64 batch rows)
    const int nw   = wid & 1;            // 0..1  (N16 of 32 gate cols)
    const bool isL0 = blockIdx.x < 64;
    const int j0   = (blockIdx.x & 63) * 8;

    const uint32_t smb = smem_u32(sm8);
    __half* ws = (__half*)sm8;

    // fragment addressing helpers (shared by both layers)
    const int arow_l = (lane & 7) + ((lane >> 3) & 1) * 8;   // + mw*16
    const int acol_l = (lane >> 4) * 8;
    const int brow_l = ((lane >> 4) & 1) * 8 + (lane & 7);   // + nw*16
    const int bcol_l = ((lane >> 3) & 1) * 8;

    if (isL0) {
        // ---- layer-0 setup: split W_hh0 slice to fp16 hi/lo (stride 520) ----
#pragma unroll 4
        for (int i = 0; i < 64; i++) {
            int idx = tx + i * 256;
            int cc = idx >> 9, k = idx & 511;
            int gg = cc >> 3, u = cc & 7;
            float w = Whh0[(size_t)(gg * H_ + j0 + u) * H_ + k];
            __half wh = __float2half(w);
            ws[cc * WS0_STR + k] = wh;
            ws[16640 + cc * WS0_STR + k] = __float2half(w - __half2float(wh));
        }
    } else {
        // ---- layer-1 setup: split [W_ih1 ; W_hh1] slice (stride 1048) ----
#pragma unroll 4
        for (int i = 0; i < 128; i++) {
            int idx = tx + i * 256;          // 0..32767
            int cc = idx >> 10, k = idx & 1023;
            int gg = cc >> 3, u = cc & 7;
            size_t row = (size_t)(gg * H_ + j0 + u) * H_;
            float w = (k < 512) ? Wih1[row + k] : Whh1[row + k - 512];
            __half wh = __float2half(w);
            ws[cc * WS1_STR + k] = wh;
            ws[33536 + cc * WS1_STR + k] = __float2half(w - __half2float(wh));
        }
        if (tx < 32) {
            int gg = tx >> 3, u = tx & 7;
            ((float*)(sm8 + BS1_OFF))[tx] =
                b_ih1[gg * H_ + j0 + u] + b_hh1[gg * H_ + j0 + u];
        }
    }
    __syncthreads();

    float accH[2][4], accL[2][4];

    for (int s = 0; s <= T_; s++) {
        if (isL0 && s < T_) {
            // ================= layer-0 step s =================
            const int t = s;
            float* xs = (float*)(sm8 + XS0_OFF);
            float* gs = (float*)(sm8 + GS0_OFF);
            float* cs = (float*)(sm8 + CS0_OFF);
            const uint32_t hsb = smb + HS0_OFF;

            // group 0: xp tile
#pragma unroll
            for (int i = 0; i < 2; i++) {
                int idx = tx + i * 256;
                int b = idx >> 3, gg = (idx >> 1) & 3, seg = idx & 1;
                uint32_t dst = smb + XS0_OFF + (uint32_t)(b * 32 + gg * 8 + seg * 4) * 4;
                CP_ASYNC16(dst, xp0 + ((size_t)b * T_ + t) * G4_ + gg * H_ + j0 + seg * 4);
            }
            CP_COMMIT();

#pragma unroll
            for (int ni = 0; ni < 2; ni++)
#pragma unroll
                for (int e = 0; e < 4; e++) { accH[ni][e] = 0.f; accL[ni][e] = 0.f; }

            if (t > 0) {
                const long long inoff = (long long)((t & 1) ^ 1) * B_ * H_;
                // groups 1..4: four 128-col chunks of h0 (fp16, single plane)
#pragma unroll
                for (int c = 0; c < 4; c++) {
#pragma unroll
                    for (int i = 0; i < 4; i++) {
                        int idx = tx + i * 256;          // 0..1023
                        int r   = idx >> 4;
                        int seg = idx & 15;
                        const __half* src = h0 + inoff + (long long)r * H_ + c * 128 + seg * 8;
                        uint32_t dst = hsb + (uint32_t)c * HC0_BYTES
                                     + (uint32_t)(r * 136 + seg * 8) * 2;
                        CP_ASYNC16(dst, src);
                    }
                    CP_COMMIT();
                }

                auto consume = [&](int c) {
                    const uint32_t hb = hsb + (uint32_t)c * HC0_BYTES;
#pragma unroll
                    for (int kk2 = 0; kk2 < 8; kk2++) {
                        uint32_t a[4], bHf[4], bLf[4];
                        uint32_t ad = hb + (uint32_t)((mw * 16 + arow_l) * 136
                                                      + kk2 * 16 + acol_l) * 2;
                        LDSM_X4(a, ad);
                        int kg = c * 8 + kk2;
                        uint32_t bd = smb + (uint32_t)((nw * 16 + brow_l) * WS0_STR
                                                       + kg * 16 + bcol_l) * 2;
                        LDSM_X4(bHf, bd);
                        LDSM_X4(bLf, bd + WS0_MATB);
#pragma unroll
                        for (int ni = 0; ni < 2; ni++) {
                            mma_f16(accH[ni], a, bHf + 2 * ni);
                            mma_f16(accL[ni], a, bLf + 2 * ni);
                        }
                    }
                };
                CP_WAIT(3); __syncthreads(); consume(0);
                CP_WAIT(2); __syncthreads(); consume(1);
                CP_WAIT(1); __syncthreads(); consume(2);
                CP_WAIT(0); __syncthreads(); consume(3);

#pragma unroll
                for (int ni = 0; ni < 2; ni++) {
                    int r = mw * 16 + (lane >> 2);
                    int cb = nw * 16 + ni * 8 + (lane & 3) * 2;
                    gs[r * 33 + cb]           = accH[ni][0] + accL[ni][0];
                    gs[r * 33 + cb + 1]       = accH[ni][1] + accL[ni][1];
                    gs[(r + 8) * 33 + cb]     = accH[ni][2] + accL[ni][2];
                    gs[(r + 8) * 33 + cb + 1] = accH[ni][3] + accL[ni][3];
                }
            } else {
                CP_WAIT(0);
            }
            __syncthreads();

            const long long outoff = (long long)(t & 1) * B_ * H_;
#pragma unroll
            for (int i = 0; i < 2; i++) {
                int e = tx + i * 256;
                int b = e >> 3, u = e & 7;
                float gi = xs[b * 32 + 0 * 8 + u];
                float gf = xs[b * 32 + 1 * 8 + u];
                float gc = xs[b * 32 + 2 * 8 + u];
                float go = xs[b * 32 + 3 * 8 + u];
                if (t > 0) {
                    gi += gs[b * 33 + 0 * 8 + u];
                    gf += gs[b * 33 + 1 * 8 + u];
                    gc += gs[b * 33 + 2 * 8 + u];
                    go += gs[b * 33 + 3 * 8 + u];
                }
                float i_ = 1.f / (1.f + expf(-gi));
                float f_ = 1.f / (1.f + expf(-gf));
                float g_ = tanhf(gc);
                float o_ = 1.f / (1.f + expf(-go));
                float cold = (t == 0) ? 0.f : cs[e];
                float cn = f_ * cold + i_ * g_;
                cs[e] = cn;
                h0[outoff + (long long)b * H_ + j0 + u] = __float2half(o_ * tanhf(cn));
            }
        } else if (!isL0 && s >= 1) {
            // ================= layer-1 step t = s-1 =================
            const int t = s - 1;
            float* gs = (float*)(sm8 + GS1_OFF);
            float* cs = (float*)(sm8 + CS1_OFF);
            float* bs = (float*)(sm8 + BS1_OFF);
            const uint32_t hsb = smb + HS1_OFF;
            const int nch = (t == 0) ? 8 : 16;   // 64-col chunks of concat K

#pragma unroll
            for (int ni = 0; ni < 2; ni++)
#pragma unroll
                for (int e = 0; e < 4; e++) { accH[ni][e] = 0.f; accL[ni][e] = 0.f; }

            const long long in0 = (long long)(t & 1) * B_ * H_;         // h0[t]
            const long long in1 = (long long)((t & 1) ^ 1) * B_ * H_;   // h1[t-1]

            auto issue = [&](int kc) {
                const __half* sh;
                int coff;
                if (kc < 8) { sh = h0 + in0; coff = kc * 64; }
                else        { sh = h1 + in1; coff = (kc - 8) * 64; }
#pragma unroll
                for (int i = 0; i < 2; i++) {
                    int idx = tx + i * 256;          // 0..511
                    int r   = idx >> 3;
                    int seg = idx & 7;
                    const __half* src = sh + (long long)r * H_ + coff + seg * 8;
                    uint32_t dst = hsb + (uint32_t)(kc & 3) * HC1_BYTES
                                 + (uint32_t)(r * 72 + seg * 8) * 2;
                    CP_ASYNC16(dst, src);
                }
                CP_COMMIT();
            };
            auto consume = [&](int kc) {
                const uint32_t hb = hsb + (uint32_t)(kc & 3) * HC1_BYTES;
#pragma unroll
                for (int kk2 = 0; kk2 < 4; kk2++) {
                    uint32_t a[4], bHf[4], bLf[4];
                    uint32_t ad = hb + (uint32_t)((mw * 16 + arow_l) * 72
                                                  + kk2 * 16 + acol_l) * 2;
                    LDSM_X4(a, ad);
                    int kg = kc * 4 + kk2;           // global k-tile 0..63
                    uint32_t bd = smb + (uint32_t)((nw * 16 + brow_l) * WS1_STR
                                                   + kg * 16 + bcol_l) * 2;
                    LDSM_X4(bHf, bd);
                    LDSM_X4(bLf, bd + WS1_MATB);
#pragma unroll
                    for (int ni = 0; ni < 2; ni++) {
                        mma_f16(accH[ni], a, bHf + 2 * ni);
                        mma_f16(accL[ni], a, bLf + 2 * ni);
                    }
                }
            };

            // 4-deep ring, issue depth 3, one syncthreads per chunk
            issue(0); issue(1); issue(2);
            CP_WAIT(2); __syncthreads();
            for (int kc = 0; kc < nch; kc++) {
                consume(kc);
                if (kc + 3 < nch) issue(kc + 3);
                else              CP_COMMIT();       // empty group keeps count
                CP_WAIT(2); __syncthreads();
            }

#pragma unroll
            for (int ni = 0; ni < 2; ni++) {
                int r = mw * 16 + (lane >> 2);
                int cb = nw * 16 + ni * 8 + (lane & 3) * 2;
                gs[r * 33 + cb]           = accH[ni][0] + accL[ni][0];
                gs[r * 33 + cb + 1]       = accH[ni][1] + accL[ni][1];
                gs[(r + 8) * 33 + cb]     = accH[ni][2] + accL[ni][2];
                gs[(r + 8) * 33 + cb + 1] = accH[ni][3] + accL[ni][3];
            }
            __syncthreads();

            const long long outoff = (long long)(t & 1) * B_ * H_;
#pragma unroll
            for (int i = 0; i < 2; i++) {
                int e = tx + i * 256;
                int b = e >> 3, u = e & 7;
                float gi = bs[0 * 8 + u] + gs[b * 33 + 0 * 8 + u];
                float gf = bs[1 * 8 + u] + gs[b * 33 + 1 * 8 + u];
                float gc = bs[2 * 8 + u] + gs[b * 33 + 2 * 8 + u];
                float go = bs[3 * 8 + u] + gs[b * 33 + 3 * 8 + u];
                float i_ = 1.f / (1.f + expf(-gi));
                float f_ = 1.f / (1.f + expf(-gf));
                float g_ = tanhf(gc);
                float o_ = 1.f / (1.f + expf(-go));
                float cold = (t == 0) ? 0.f : cs[e];
                float cn = f_ * cold + i_ * g_;
                cs[e] = cn;
                h1[outoff + (long long)b * H_ + j0 + u] = __float2half(o_ * tanhf(cn));
            }
        }

        // ---- grid barrier between stages ----
        if (s < T_) {
            __syncthreads();
            if (tx == 0) {
                unsigned target = (unsigned)(s + 1) * (unsigned)gridDim.x;
                asm volatile("red.release.gpu.global.add.u32 [%0], %1;"
                             :: "l"(bar), "r"(1u) : "memory");
                unsigned v;
                do {
                    asm volatile("ld.acquire.gpu.global.u32 %0, [%1];"
                                 : "=r"(v) : "l"(bar) : "memory");
                } while (v < target);
            }
            __syncthreads();
        }
    }
}

// ---------------------------------------------------------------------------
// Final FC on fp16 h
// ---------------------------------------------------------------------------
__global__ __launch_bounds__(128) void fc_kernel(
    const __half* __restrict__ h, const float* __restrict__ Wfc,
    const float* __restrict__ bfc, float* __restrict__ out)
{
    __shared__ float hrow[H_];
    int b = blockIdx.x;
    for (int k = threadIdx.x; k < H_; k += 128)
        hrow[k] = __half2float(h[b * H_ + k]);
    __syncthreads();

    int o = threadIdx.x;
    float s = bfc[o];
    const float4* w4 = reinterpret_cast<const float4*>(Wfc + (size_t)o * H_);
    const float4* h4 = reinterpret_cast<const float4*>(hrow);
#pragma unroll 4
    for (int k = 0; k < H_ / 4; k++) {
        float4 w = w4[k];
        float4 hh = h4[k];
        s += w.x * hh.x + w.y * hh.y + w.z * hh.z + w.w * hh.w;
    }
    out[b * OUT_ + o] = s;
}

// ---------------------------------------------------------------------------
extern "C" void kernel_launch(void* const* d_in, const int* in_sizes, int n_in,
                              void* d_out, int out_size)
{
    const float* x     = (const float*)d_in[0];
    const float* W_ih0 = (const float*)d_in[1];
    const float* W_hh0 = (const float*)d_in[2];
    const float* b_ih0 = (const float*)d_in[3];
    const float* b_hh0 = (const float*)d_in[4];
    const float* W_ih1 = (const float*)d_in[5];
    const float* W_hh1 = (const float*)d_in[6];
    const float* b_ih1 = (const float*)d_in[7];
    const float* b_hh1 = (const float*)d_in[8];
    const float* W_fc  = (const float*)d_in[9];
    const float* b_fc  = (const float*)d_in[10];
    float* out = (float*)d_out;

    float* xp;
    unsigned* bar;
    __nv_bfloat16 *xhi, *xlo, *whi, *wlo;
    __half *h0, *h1;
    cudaGetSymbolAddress((void**)&xp,  g_xp);
    cudaGetSymbolAddress((void**)&bar, g_bar);
    cudaGetSymbolAddress((void**)&xhi, g_Xhi);
    cudaGetSymbolAddress((void**)&xlo, g_Xlo);
    cudaGetSymbolAddress((void**)&whi, g_Whi);
    cudaGetSymbolAddress((void**)&wlo, g_Wlo);
    cudaGetSymbolAddress((void**)&h0,  g_h0);
    cudaGetSymbolAddress((void**)&h1,  g_h1);

    cudaFuncSetAttribute(gemm_mma_kernel,
                         cudaFuncAttributeMaxDynamicSharedMemorySize, GEMM_SMEM_BYTES);
    cudaFuncSetAttribute(lstm_fused_kernel,
                         cudaFuncAttributeMaxDynamicSharedMemorySize, FUSED_SMEM);

    dim3 mma_grid(G4_ / 128, M_ / 128);   // (16, 256)

    // layer-0 xp GEMM (K=128)
    {
        int nA = M_ * IN_;
        int nW = G4_ * IN_;
        split_bf16_kernel<<<(nA + 255) / 256, 256>>>(x, xhi, xlo, nA);
        split_bf16_kernel<<<(nW + 255) / 256, 256>>>(W_ih0, whi, wlo, nW);
        gemm_mma_kernel<<<mma_grid, 256, GEMM_SMEM_BYTES>>>(xhi, xlo, whi, wlo,
                                                            b_ih0, b_hh0, xp, IN_);
    }
    bar_init_kernel<<<1, 1>>>();

    // fused two-layer recurrence (fp16x2)
    lstm_fused_kernel<<<FBLK, RTHR, FUSED_SMEM>>>(
        xp, W_hh0, W_ih1, W_hh1, b_ih1, b_hh1, h0, h1, bar);

    // final FC on h1[t=511] (parity 1)
    fc_kernel<<<B_, 128>>>(h1 + (size_t)B_ * H_, W_fc, b_fc, out);
}

// round 10
// speedup vs baseline: 4.1260x; 1.2102x over previous
#include <cuda_runtime.h>
#include <cuda_bf16.h>
#include <cuda_fp16.h>
#include <math.h>
#include <stdint.h>

#define B_   64
#define T_   512
#define IN_  128
#define H_   512
#define G4_  2048   // 4*H
#define OUT_ 128
#define M_   (B_ * T_)   // 32768

#define FBLK 128    // fused grid: 64 layer-0 + 64 layer-1 blocks
#define RTHR 256

// ---------------- scratch (static device memory; no allocs) ----------------
__device__ float g_xp[(size_t)M_ * G4_];            // layer-0 gate preactivations
__device__ unsigned int g_bar;                      // grid barrier counter

__device__ __nv_bfloat16 g_Xhi[(size_t)M_ * IN_];   // x split (front GEMM, bf16x3)
__device__ __nv_bfloat16 g_Xlo[(size_t)M_ * IN_];
__device__ __nv_bfloat16 g_Whi[(size_t)G4_ * IN_];  // W_ih0 split
__device__ __nv_bfloat16 g_Wlo[(size_t)G4_ * IN_];
__device__ __half g_h0[2 * B_ * H_];                // layer-0 h ping-pong (fp16)
__device__ __half g_h1[2 * B_ * H_];                // layer-1 h ping-pong (fp16)

// ======================= helpers ==============================
__device__ __forceinline__ uint32_t smem_u32(const void* p) {
    uint32_t a;
    asm("{ .reg .u64 t; cvta.to.shared.u64 t, %1; cvt.u32.u64 %0, t; }"
        : "=r"(a) : "l"(p));
    return a;
}

#define LDSM_X4(r, addr) \
    asm volatile("ldmatrix.sync.aligned.m8n8.x4.shared.b16 {%0,%1,%2,%3}, [%4];" \
        : "=r"((r)[0]), "=r"((r)[1]), "=r"((r)[2]), "=r"((r)[3]) : "r"(addr))
#define LDSM_X2(r, addr) \
    asm volatile("ldmatrix.sync.aligned.m8n8.x2.shared.b16 {%0,%1}, [%2];" \
        : "=r"((r)[0]), "=r"((r)[1]) : "r"(addr))

__device__ __forceinline__ void mma_bf16(float* d, const uint32_t* a, const uint32_t* b) {
    asm volatile("mma.sync.aligned.m16n8k16.row.col.f32.bf16.bf16.f32 "
        "{%0,%1,%2,%3}, {%4,%5,%6,%7}, {%8,%9}, {%0,%1,%2,%3};"
        : "+f"(d[0]), "+f"(d[1]), "+f"(d[2]), "+f"(d[3])
        : "r"(a[0]), "r"(a[1]), "r"(a[2]), "r"(a[3]), "r"(b[0]), "r"(b[1]));
}
__device__ __forceinline__ void mma_f16(float* d, const uint32_t* a, const uint32_t* b) {
    asm volatile("mma.sync.aligned.m16n8k16.row.col.f32.f16.f16.f32 "
        "{%0,%1,%2,%3}, {%4,%5,%6,%7}, {%8,%9}, {%0,%1,%2,%3};"
        : "+f"(d[0]), "+f"(d[1]), "+f"(d[2]), "+f"(d[3])
        : "r"(a[0]), "r"(a[1]), "r"(a[2]), "r"(a[3]), "r"(b[0]), "r"(b[1]));
}

#define CP_ASYNC16(dst, src) \
    asm volatile("cp.async.cg.shared.global [%0], [%1], 16;" :: "r"(dst), "l"(src))
#define CP_COMMIT() asm volatile("cp.async.commit_group;" ::: "memory")
#define CP_WAIT(n)  asm volatile("cp.async.wait_group %0;" :: "n"(n) : "memory")

// ---------------------------------------------------------------------------
// fp32 -> (hi, lo) bf16 split; optionally resets the grid barrier counter
// ---------------------------------------------------------------------------
__global__ __launch_bounds__(256) void split_bf16_kernel(
    const float* __restrict__ in, __nv_bfloat16* __restrict__ hi,
    __nv_bfloat16* __restrict__ lo, int n, unsigned* bar_reset)
{
    if (bar_reset && blockIdx.x == 0 && threadIdx.x == 0) *bar_reset = 0u;
    int i = blockIdx.x * 256 + threadIdx.x;
    if (i < n) {
        float v = in[i];
        __nv_bfloat16 h = __float2bfloat16(v);
        hi[i] = h;
        lo[i] = __float2bfloat16(v - __bfloat162float(h));
    }
}

// ---------------------------------------------------------------------------
// bf16x3 GEMM via mma.sync (layer-0 xp only; unchanged, passing since R3)
// ---------------------------------------------------------------------------
#define GSTRIDE 40
#define SMAT    (128 * GSTRIDE)
#define SSTAGE  (4 * SMAT)
#define GEMM_SMEM_BYTES (2 * SSTAGE * 2 + 128 * 4)

__global__ __launch_bounds__(256) void gemm_mma_kernel(
    const __nv_bfloat16* __restrict__ Ahi, const __nv_bfloat16* __restrict__ Alo,
    const __nv_bfloat16* __restrict__ Whi, const __nv_bfloat16* __restrict__ Wlo,
    const float* __restrict__ b1, const float* __restrict__ b2,
    float* __restrict__ C, int K)
{
    extern __shared__ __nv_bfloat16 sm[];
    float* biass = (float*)(sm + 2 * SSTAGE);

    const int tid  = threadIdx.x;
    const int wid  = tid >> 5;
    const int lane = tid & 31;
    const int wm   = wid >> 2;
    const int wn   = wid & 3;
    const int m0   = blockIdx.y * 128;
    const int n0   = blockIdx.x * 128;

    if (tid < 128) biass[tid] = b1[n0 + tid] + b2[n0 + tid];

    const int K8 = K >> 3;
    const uint4* gA[2] = { (const uint4*)Ahi, (const uint4*)Alo };
    const uint4* gW[2] = { (const uint4*)Whi, (const uint4*)Wlo };
    const uint32_t smb = smem_u32(sm);

    auto prefetch = [&](int kt, int st) {
        const int kk8 = kt * 4;
        const uint32_t sbase = smb + (uint32_t)st * (SSTAGE * 2);
#pragma unroll
        for (int hl = 0; hl < 2; hl++) {
#pragma unroll
            for (int i = 0; i < 2; i++) {
                int idx = tid + i * 256;
                int r = idx >> 2, j = idx & 3;
                uint32_t dst = sbase + (uint32_t)(hl * SMAT + r * GSTRIDE) * 2 + j * 16;
                CP_ASYNC16(dst, gA[hl] + (size_t)(m0 + r) * K8 + kk8 + j);
            }
#pragma unroll
            for (int i = 0; i < 2; i++) {
                int idx = tid + i * 256;
                int r = idx >> 2, j = idx & 3;
                uint32_t dst = sbase + (uint32_t)((2 + hl) * SMAT + r * GSTRIDE) * 2 + j * 16;
                CP_ASYNC16(dst, gW[hl] + (size_t)(n0 + r) * K8 + kk8 + j);
            }
        }
        CP_COMMIT();
    };

    float acc[4][4][4];
#pragma unroll
    for (int mi = 0; mi < 4; mi++)
#pragma unroll
        for (int ni = 0; ni < 4; ni++)
#pragma unroll
            for (int e = 0; e < 4; e++) acc[mi][ni][e] = 0.f;

    const int KT = K / 32;
    prefetch(0, 0);

    for (int kt = 0; kt < KT; kt++) {
        if (kt + 1 < KT) { prefetch(kt + 1, (kt + 1) & 1); CP_WAIT(1); }
        else             { CP_WAIT(0); }
        __syncthreads();

        const uint32_t sbase = smb + (uint32_t)(kt & 1) * (SSTAGE * 2);
#pragma unroll
        for (int ks = 0; ks < 2; ks++) {
            uint32_t aH[4][4], aL[4][4], bH[4][2], bL[4][2];

            const int arow = wm * 64 + (lane & 7) + ((lane >> 3) & 1) * 8;
            const int acol = ks * 16 + (lane >> 4) * 8;
#pragma unroll
            for (int mi = 0; mi < 4; mi++) {
                uint32_t ad = sbase + (uint32_t)((arow + mi * 16) * GSTRIDE + acol) * 2;
                LDSM_X4(aH[mi], ad);
                LDSM_X4(aL[mi], ad + SMAT * 2);
            }
            const int l16  = lane & 15;
            const int brow = wn * 32 + (l16 & 7);
            const int bcol = ks * 16 + (l16 >> 3) * 8;
#pragma unroll
            for (int ni = 0; ni < 4; ni++) {
                uint32_t bd = sbase + (uint32_t)(2 * SMAT + (brow + ni * 8) * GSTRIDE + bcol) * 2;
                LDSM_X2(bH[ni], bd);
                LDSM_X2(bL[ni], bd + SMAT * 2);
            }
#pragma unroll
            for (int mi = 0; mi < 4; mi++)
#pragma unroll
                for (int ni = 0; ni < 4; ni++) {
                    mma_bf16(acc[mi][ni], aH[mi], bH[ni]);
                    mma_bf16(acc[mi][ni], aH[mi], bL[ni]);
                    mma_bf16(acc[mi][ni], aL[mi], bH[ni]);
                }
        }
        __syncthreads();
    }

#pragma unroll
    for (int mi = 0; mi < 4; mi++) {
        const int r0 = m0 + wm * 64 + mi * 16 + (lane >> 2);
#pragma unroll
        for (int ni = 0; ni < 4; ni++) {
            const int c = wn * 32 + ni * 8 + (lane & 3) * 2;
            float2 v0, v1;
            v0.x = acc[mi][ni][0] + biass[c];
            v0.y = acc[mi][ni][1] + biass[c + 1];
            v1.x = acc[mi][ni][2] + biass[c];
            v1.y = acc[mi][ni][3] + biass[c + 1];
            *(float2*)&C[(size_t)r0 * G4_ + n0 + c]       = v0;
            *(float2*)&C[(size_t)(r0 + 8) * G4_ + n0 + c] = v1;
        }
    }
}

// ---------------------------------------------------------------------------
// FUSED two-layer persistent LSTM, pure fp16 (h fp16, W single-plane fp16).
// Blocks 0..63  : layer 0 (K=512 vs h0[t-1]); 4x128-col chunks resident.
// Blocks 64..127: layer 1 (K=1024 vs [h0[t] ; h1[t-1]]); 8x128-col chunks
//                 through a 4-deep cp.async ring (latency-covering chunks).
// Per k16 tile per warp: 1 A-LDSM_X4 + 1 B-LDSM_X4 + 2 HMMA.
// ---------------------------------------------------------------------------
// layer-0 SMEM layout
#define WS0_STR   520
#define HS0_OFF   33280u            // 32*520*2
#define HC0_BYTES 17408u            // 64*136*2 per 128-col chunk
#define XS0_OFF   102912u           // HS0_OFF + 4*HC0_BYTES
#define GS0_OFF   111104u           // + 64*32*4
#define CS0_OFF   119552u           // + 64*33*4
// layer-1 SMEM layout
#define WS1_STR   1048
#define HS1_OFF   67072u            // 32*1048*2
#define HC1_BYTES 17408u            // 64*136*2 per 128-col chunk
#define GS1_OFF   136704u           // HS1_OFF + 4*HC1_BYTES
#define CS1_OFF   145152u
#define BS1_OFF   147200u
#define FUSED_SMEM 147456

__global__ __launch_bounds__(RTHR, 1) void lstm_fused_kernel(
    const float* __restrict__ xp0, const float* __restrict__ Whh0,
    const float* __restrict__ Wih1, const float* __restrict__ Whh1,
    const float* __restrict__ b_ih1, const float* __restrict__ b_hh1,
    __half* __restrict__ h0, __half* __restrict__ h1,
    unsigned* __restrict__ bar)
{
    extern __shared__ char sm8[];
    const int tx   = threadIdx.x;
    const int wid  = tx >> 5;
    const int lane = tx & 31;
    const int mw   = wid >> 1;           // 0..3  (M16 of 64 batch rows)
    const int nw   = wid & 1;            // 0..1  (N16 of 32 gate cols)
    const bool isL0 = blockIdx.x < 64;
    const int j0   = (blockIdx.x & 63) * 8;

    const uint32_t smb = smem_u32(sm8);
    __half* ws = (__half*)sm8;

    // fragment addressing helpers
    const int arow_l = (lane & 7) + ((lane >> 3) & 1) * 8;   // + mw*16
    const int acol_l = (lane >> 4) * 8;
    const int brow_l = ((lane >> 4) & 1) * 8 + (lane & 7);   // + nw*16
    const int bcol_l = ((lane >> 3) & 1) * 8;

    if (isL0) {
        // ---- layer-0 setup: W_hh0 slice -> fp16 (stride 520) ----
#pragma unroll 4
        for (int i = 0; i < 64; i++) {
            int idx = tx + i * 256;
            int cc = idx >> 9, k = idx & 511;
            int gg = cc >> 3, u = cc & 7;
            ws[cc * WS0_STR + k] =
                __float2half(Whh0[(size_t)(gg * H_ + j0 + u) * H_ + k]);
        }
    } else {
        // ---- layer-1 setup: [W_ih1 ; W_hh1] slice -> fp16 (stride 1048) ----
#pragma unroll 4
        for (int i = 0; i < 128; i++) {
            int idx = tx + i * 256;          // 0..32767
            int cc = idx >> 10, k = idx & 1023;
            int gg = cc >> 3, u = cc & 7;
            size_t row = (size_t)(gg * H_ + j0 + u) * H_;
            float w = (k < 512) ? Wih1[row + k] : Whh1[row + k - 512];
            ws[cc * WS1_STR + k] = __float2half(w);
        }
        if (tx < 32) {
            int gg = tx >> 3, u = tx & 7;
            ((float*)(sm8 + BS1_OFF))[tx] =
                b_ih1[gg * H_ + j0 + u] + b_hh1[gg * H_ + j0 + u];
        }
    }
    __syncthreads();

    float acc[2][4];

    for (int s = 0; s <= T_; s++) {
        if (isL0 && s < T_) {
            // ================= layer-0 step s =================
            const int t = s;
            float* xs = (float*)(sm8 + XS0_OFF);
            float* gs = (float*)(sm8 + GS0_OFF);
            float* cs = (float*)(sm8 + CS0_OFF);
            const uint32_t hsb = smb + HS0_OFF;

            // group 0: xp tile
#pragma unroll
            for (int i = 0; i < 2; i++) {
                int idx = tx + i * 256;
                int b = idx >> 3, gg = (idx >> 1) & 3, seg = idx & 1;
                uint32_t dst = smb + XS0_OFF + (uint32_t)(b * 32 + gg * 8 + seg * 4) * 4;
                CP_ASYNC16(dst, xp0 + ((size_t)b * T_ + t) * G4_ + gg * H_ + j0 + seg * 4);
            }
            CP_COMMIT();

#pragma unroll
            for (int ni = 0; ni < 2; ni++)
#pragma unroll
                for (int e = 0; e < 4; e++) acc[ni][e] = 0.f;

            if (t > 0) {
                const long long inoff = (long long)((t & 1) ^ 1) * B_ * H_;
                // groups 1..4: four 128-col chunks of h0 (fp16)
#pragma unroll
                for (int c = 0; c < 4; c++) {
#pragma unroll
                    for (int i = 0; i < 4; i++) {
                        int idx = tx + i * 256;          // 0..1023
                        int r   = idx >> 4;
                        int seg = idx & 15;
                        const __half* src = h0 + inoff + (long long)r * H_ + c * 128 + seg * 8;
                        uint32_t dst = hsb + (uint32_t)c * HC0_BYTES
                                     + (uint32_t)(r * 136 + seg * 8) * 2;
                        CP_ASYNC16(dst, src);
                    }
                    CP_COMMIT();
                }

                auto consume = [&](int c) {
                    const uint32_t hb = hsb + (uint32_t)c * HC0_BYTES;
#pragma unroll
                    for (int kk2 = 0; kk2 < 8; kk2++) {
                        uint32_t a[4], bf[4];
                        uint32_t ad = hb + (uint32_t)((mw * 16 + arow_l) * 136
                                                      + kk2 * 16 + acol_l) * 2;
                        LDSM_X4(a, ad);
                        int kg = c * 8 + kk2;
                        uint32_t bd = smb + (uint32_t)((nw * 16 + brow_l) * WS0_STR
                                                       + kg * 16 + bcol_l) * 2;
                        LDSM_X4(bf, bd);
                        mma_f16(acc[0], a, bf);
                        mma_f16(acc[1], a, bf + 2);
                    }
                };
                CP_WAIT(3); __syncthreads(); consume(0);
                CP_WAIT(2); __syncthreads(); consume(1);
                CP_WAIT(1); __syncthreads(); consume(2);
                CP_WAIT(0); __syncthreads(); consume(3);

#pragma unroll
                for (int ni = 0; ni < 2; ni++) {
                    int r = mw * 16 + (lane >> 2);
                    int cb = nw * 16 + ni * 8 + (lane & 3) * 2;
                    gs[r * 33 + cb]           = acc[ni][0];
                    gs[r * 33 + cb + 1]       = acc[ni][1];
                    gs[(r + 8) * 33 + cb]     = acc[ni][2];
                    gs[(r + 8) * 33 + cb + 1] = acc[ni][3];
                }
            } else {
                CP_WAIT(0);
            }
            __syncthreads();

            const long long outoff = (long long)(t & 1) * B_ * H_;
#pragma unroll
            for (int i = 0; i < 2; i++) {
                int e = tx + i * 256;
                int b = e >> 3, u = e & 7;
                float gi = xs[b * 32 + 0 * 8 + u];
                float gf = xs[b * 32 + 1 * 8 + u];
                float gc = xs[b * 32 + 2 * 8 + u];
                float go = xs[b * 32 + 3 * 8 + u];
                if (t > 0) {
                    gi += gs[b * 33 + 0 * 8 + u];
                    gf += gs[b * 33 + 1 * 8 + u];
                    gc += gs[b * 33 + 2 * 8 + u];
                    go += gs[b * 33 + 3 * 8 + u];
                }
                float i_ = 1.f / (1.f + expf(-gi));
                float f_ = 1.f / (1.f + expf(-gf));
                float g_ = tanhf(gc);
                float o_ = 1.f / (1.f + expf(-go));
                float cold = (t == 0) ? 0.f : cs[e];
                float cn = f_ * cold + i_ * g_;
                cs[e] = cn;
                h0[outoff + (long long)b * H_ + j0 + u] = __float2half(o_ * tanhf(cn));
            }
        } else if (!isL0 && s >= 1) {
            // ================= layer-1 step t = s-1 =================
            const int t = s - 1;
            float* gs = (float*)(sm8 + GS1_OFF);
            float* cs = (float*)(sm8 + CS1_OFF);
            float* bs = (float*)(sm8 + BS1_OFF);
            const uint32_t hsb = smb + HS1_OFF;
            const int nch = (t == 0) ? 4 : 8;    // 128-col chunks of concat K

#pragma unroll
            for (int ni = 0; ni < 2; ni++)
#pragma unroll
                for (int e = 0; e < 4; e++) acc[ni][e] = 0.f;

            const long long in0 = (long long)(t & 1) * B_ * H_;         // h0[t]
            const long long in1 = (long long)((t & 1) ^ 1) * B_ * H_;   // h1[t-1]

            auto issue = [&](int kc) {
                const __half* sh;
                int coff;
                if (kc < 4) { sh = h0 + in0; coff = kc * 128; }
                else        { sh = h1 + in1; coff = (kc - 4) * 128; }
#pragma unroll
                for (int i = 0; i < 4; i++) {
                    int idx = tx + i * 256;          // 0..1023
                    int r   = idx >> 4;
                    int seg = idx & 15;
                    const __half* src = sh + (long long)r * H_ + coff + seg * 8;
                    uint32_t dst = hsb + (uint32_t)(kc & 3) * HC1_BYTES
                                 + (uint32_t)(r * 136 + seg * 8) * 2;
                    CP_ASYNC16(dst, src);
                }
                CP_COMMIT();
            };
            auto consume = [&](int kc) {
                const uint32_t hb = hsb + (uint32_t)(kc & 3) * HC1_BYTES;
#pragma unroll
                for (int kk2 = 0; kk2 < 8; kk2++) {
                    uint32_t a[4], bf[4];
                    uint32_t ad = hb + (uint32_t)((mw * 16 + arow_l) * 136
                                                  + kk2 * 16 + acol_l) * 2;
                    LDSM_X4(a, ad);
                    int kg = kc * 8 + kk2;           // global k-tile 0..63
                    uint32_t bd = smb + (uint32_t)((nw * 16 + brow_l) * WS1_STR
                                                   + kg * 16 + bcol_l) * 2;
                    LDSM_X4(bf, bd);
                    mma_f16(acc[0], a, bf);
                    mma_f16(acc[1], a, bf + 2);
                }
            };

            // 4-deep ring, issue depth 3, one syncthreads per chunk
            issue(0); issue(1); issue(2);
            CP_WAIT(2); __syncthreads();
            for (int kc = 0; kc < nch; kc++) {
                consume(kc);
                if (kc + 3 < nch) issue(kc + 3);
                else              CP_COMMIT();       // empty group keeps count
                CP_WAIT(2); __syncthreads();
            }

#pragma unroll
            for (int ni = 0; ni < 2; ni++) {
                int r = mw * 16 + (lane >> 2);
                int cb = nw * 16 + ni * 8 + (lane & 3) * 2;
                gs[r * 33 + cb]           = acc[ni][0];
                gs[r * 33 + cb + 1]       = acc[ni][1];
                gs[(r + 8) * 33 + cb]     = acc[ni][2];
                gs[(r + 8) * 33 + cb + 1] = acc[ni][3];
            }
            __syncthreads();

            const long long outoff = (long long)(t & 1) * B_ * H_;
#pragma unroll
            for (int i = 0; i < 2; i++) {
                int e = tx + i * 256;
                int b = e >> 3, u = e & 7;
                float gi = bs[0 * 8 + u] + gs[b * 33 + 0 * 8 + u];
                float gf = bs[1 * 8 + u] + gs[b * 33 + 1 * 8 + u];
                float gc = bs[2 * 8 + u] + gs[b * 33 + 2 * 8 + u];
                float go = bs[3 * 8 + u] + gs[b * 33 + 3 * 8 + u];
                float i_ = 1.f / (1.f + expf(-gi));
                float f_ = 1.f / (1.f + expf(-gf));
                float g_ = tanhf(gc);
                float o_ = 1.f / (1.f + expf(-go));
                float cold = (t == 0) ? 0.f : cs[e];
                float cn = f_ * cold + i_ * g_;
                cs[e] = cn;
                h1[outoff + (long long)b * H_ + j0 + u] = __float2half(o_ * tanhf(cn));
            }
        }

        // ---- grid barrier between stages ----
        if (s < T_) {
            __syncthreads();
            if (tx == 0) {
                unsigned target = (unsigned)(s + 1) * (unsigned)gridDim.x;
                asm volatile("red.release.gpu.global.add.u32 [%0], %1;"
                             :: "l"(bar), "r"(1u) : "memory");
                unsigned v;
                do {
                    asm volatile("ld.acquire.gpu.global.u32 %0, [%1];"
                                 : "=r"(v) : "l"(bar) : "memory");
                } while (v < target);
            }
            __syncthreads();
        }
    }
}

// ---------------------------------------------------------------------------
// Final FC on fp16 h
// ---------------------------------------------------------------------------
__global__ __launch_bounds__(128) void fc_kernel(
    const __half* __restrict__ h, const float* __restrict__ Wfc,
    const float* __restrict__ bfc, float* __restrict__ out)
{
    __shared__ float hrow[H_];
    int b = blockIdx.x;
    for (int k = threadIdx.x; k < H_; k += 128)
        hrow[k] = __half2float(h[b * H_ + k]);
    __syncthreads();

    int o = threadIdx.x;
    float s = bfc[o];
    const float4* w4 = reinterpret_cast<const float4*>(Wfc + (size_t)o * H_);
    const float4* h4 = reinterpret_cast<const float4*>(hrow);
#pragma unroll 4
    for (int k = 0; k < H_ / 4; k++) {
        float4 w = w4[k];
        float4 hh = h4[k];
        s += w.x * hh.x + w.y * hh.y + w.z * hh.z + w.w * hh.w;
    }
    out[b * OUT_ + o] = s;
}

// ---------------------------------------------------------------------------
extern "C" void kernel_launch(void* const* d_in, const int* in_sizes, int n_in,
                              void* d_out, int out_size)
{
    const float* x     = (const float*)d_in[0];
    const float* W_ih0 = (const float*)d_in[1];
    const float* W_hh0 = (const float*)d_in[2];
    const float* b_ih0 = (const float*)d_in[3];
    const float* b_hh0 = (const float*)d_in[4];
    const float* W_ih1 = (const float*)d_in[5];
    const float* W_hh1 = (const float*)d_in[6];
    const float* b_ih1 = (const float*)d_in[7];
    const float* b_hh1 = (const float*)d_in[8];
    const float* W_fc  = (const float*)d_in[9];
    const float* b_fc  = (const float*)d_in[10];
    float* out = (float*)d_out;

    float* xp;
    unsigned* bar;
    __nv_bfloat16 *xhi, *xlo, *whi, *wlo;
    __half *h0, *h1;
    cudaGetSymbolAddress((void**)&xp,  g_xp);
    cudaGetSymbolAddress((void**)&bar, g_bar);
    cudaGetSymbolAddress((void**)&xhi, g_Xhi);
    cudaGetSymbolAddress((void**)&xlo, g_Xlo);
    cudaGetSymbolAddress((void**)&whi, g_Whi);
    cudaGetSymbolAddress((void**)&wlo, g_Wlo);
    cudaGetSymbolAddress((void**)&h0,  g_h0);
    cudaGetSymbolAddress((void**)&h1,  g_h1);

    cudaFuncSetAttribute(gemm_mma_kernel,
                         cudaFuncAttributeMaxDynamicSharedMemorySize, GEMM_SMEM_BYTES);
    cudaFuncSetAttribute(lstm_fused_kernel,
                         cudaFuncAttributeMaxDynamicSharedMemorySize, FUSED_SMEM);

    dim3 mma_grid(G4_ / 128, M_ / 128);   // (16, 256)

    // layer-0 xp GEMM (K=128); first split also resets the grid barrier
    {
        int nA = M_ * IN_;
        int nW = G4_ * IN_;
        split_bf16_kernel<<<(nA + 255) / 256, 256>>>(x, xhi, xlo, nA, bar);
        split_bf16_kernel<<<(nW + 255) / 256, 256>>>(W_ih0, whi, wlo, nW, nullptr);
        gemm_mma_kernel<<<mma_grid, 256, GEMM_SMEM_BYTES>>>(xhi, xlo, whi, wlo,
                                                            b_ih0, b_hh0, xp, IN_);
    }

    // fused two-layer recurrence (pure fp16)
    lstm_fused_kernel<<<FBLK, RTHR, FUSED_SMEM>>>(
        xp, W_hh0, W_ih1, W_hh1, b_ih1, b_hh1, h0, h1, bar);

    // final FC on h1[t=511] (parity 1)
    fc_kernel<<<B_, 128>>>(h1 + (size_t)B_ * H_, W_fc, b_fc, out);
}